// round 9
// baseline (speedup 1.0000x reference)
#include <cuda_runtime.h>
#include <math.h>
#include <stdint.h>

// Problem constants
#define BB     2
#define SS     2048
#define DMODEL 2048
#define LAT    512
#define NHD    16
#define HD     128
#define PHD    64
#define DQK    192     // HD + PHD
#define MROWS  4096    // BB * SS

// ---------------- scratch (static device globals; no allocation) ----------
__device__ float g_latent[MROWS * (3 * LAT)];   // [4096,1536]
__device__ float g_qmain [MROWS * DMODEL];      // [4096,2048]
__device__ float g_kmain [MROWS * DMODEL];
__device__ float g_vmain [MROWS * DMODEL];
__device__ float g_posq  [MROWS * (NHD * PHD)]; // [4096,1024]
__device__ float g_posk  [MROWS * PHD];         // [4096,64]
__device__ float g_attn  [MROWS * DMODEL];      // [b,s,h,d] packed

// ======================= generic SGEMM + bias ==============================
__device__ __forceinline__
void sgemm_core(const float* __restrict__ A, int lda, int aoff,
                const float* __restrict__ W, int ldw,
                const float* __restrict__ bias,
                float* __restrict__ C, int ldc,
                int N, int K)
{
    __shared__ float As[2][8][128];   // transposed A tile
    __shared__ float Bs[2][8][128];

    const int tid  = threadIdx.x;
    const int m0   = blockIdx.y * 128;
    const int n0   = blockIdx.x * 128;

    const int arow = tid >> 1;          // 0..127
    const int acol = (tid & 1) * 4;     // 0 or 4
    const int brow = tid >> 5;          // 0..7
    const int bcol = (tid & 31) * 4;    // 0..124

    const int tx = tid & 15;
    const int ty = tid >> 4;

    float acc[8][8];
#pragma unroll
    for (int i = 0; i < 8; i++)
#pragma unroll
        for (int j = 0; j < 8; j++) acc[i][j] = 0.0f;

    const float* Aptr = A + (long)(m0 + arow) * lda + aoff + acol;
    const float* Wptr = W + (long)brow * ldw + n0 + bcol;
    const bool bvalid = (n0 + bcol) < N;

    // prologue: tile 0 -> buffer 0
    {
        float4 a = *(const float4*)(Aptr);
        float4 b = bvalid ? *(const float4*)(Wptr)
                          : make_float4(0.f, 0.f, 0.f, 0.f);
        As[0][acol + 0][arow] = a.x;
        As[0][acol + 1][arow] = a.y;
        As[0][acol + 2][arow] = a.z;
        As[0][acol + 3][arow] = a.w;
        *(float4*)&Bs[0][brow][bcol] = b;
    }
    __syncthreads();

    int nbuf = 1;
    for (int kt = 8; kt < K; kt += 8) {
        float4 an = *(const float4*)(Aptr + kt);
        float4 bn = bvalid ? *(const float4*)(Wptr + (long)kt * ldw)
                           : make_float4(0.f, 0.f, 0.f, 0.f);

        const int cb = nbuf ^ 1;   // compute buffer
#pragma unroll
        for (int k = 0; k < 8; k++) {
            float4 a0 = *(const float4*)&As[cb][k][ty * 4];
            float4 a1 = *(const float4*)&As[cb][k][64 + ty * 4];
            float4 b0 = *(const float4*)&Bs[cb][k][tx * 4];
            float4 b1 = *(const float4*)&Bs[cb][k][64 + tx * 4];
            float ar[8] = {a0.x, a0.y, a0.z, a0.w, a1.x, a1.y, a1.z, a1.w};
            float br[8] = {b0.x, b0.y, b0.z, b0.w, b1.x, b1.y, b1.z, b1.w};
#pragma unroll
            for (int i = 0; i < 8; i++)
#pragma unroll
                for (int j = 0; j < 8; j++)
                    acc[i][j] = fmaf(ar[i], br[j], acc[i][j]);
        }

        As[nbuf][acol + 0][arow] = an.x;
        As[nbuf][acol + 1][arow] = an.y;
        As[nbuf][acol + 2][arow] = an.z;
        As[nbuf][acol + 3][arow] = an.w;
        *(float4*)&Bs[nbuf][brow][bcol] = bn;
        __syncthreads();
        nbuf ^= 1;
    }

    {
        const int cb = nbuf ^ 1;
#pragma unroll
        for (int k = 0; k < 8; k++) {
            float4 a0 = *(const float4*)&As[cb][k][ty * 4];
            float4 a1 = *(const float4*)&As[cb][k][64 + ty * 4];
            float4 b0 = *(const float4*)&Bs[cb][k][tx * 4];
            float4 b1 = *(const float4*)&Bs[cb][k][64 + tx * 4];
            float ar[8] = {a0.x, a0.y, a0.z, a0.w, a1.x, a1.y, a1.z, a1.w};
            float br[8] = {b0.x, b0.y, b0.z, b0.w, b1.x, b1.y, b1.z, b1.w};
#pragma unroll
            for (int i = 0; i < 8; i++)
#pragma unroll
                for (int j = 0; j < 8; j++)
                    acc[i][j] = fmaf(ar[i], br[j], acc[i][j]);
        }
    }

    const int nc0 = n0 + tx * 4;
    const int nc1 = n0 + 64 + tx * 4;
    const bool v0 = nc0 < N;
    const bool v1 = nc1 < N;
    float4 bb0 = v0 ? *(const float4*)&bias[nc0] : make_float4(0,0,0,0);
    float4 bb1 = v1 ? *(const float4*)&bias[nc1] : make_float4(0,0,0,0);

#pragma unroll
    for (int g = 0; g < 2; g++) {
#pragma unroll
        for (int i = 0; i < 4; i++) {
            long m = m0 + g * 64 + ty * 4 + i;
            const float* ac = acc[g * 4 + i];
            if (v0) {
                float4 o = make_float4(ac[0] + bb0.x, ac[1] + bb0.y,
                                       ac[2] + bb0.z, ac[3] + bb0.w);
                *(float4*)&C[m * ldc + nc0] = o;
            }
            if (v1) {
                float4 o = make_float4(ac[4] + bb1.x, ac[5] + bb1.y,
                                       ac[6] + bb1.z, ac[7] + bb1.w);
                *(float4*)&C[m * ldc + nc1] = o;
            }
        }
    }
}

__global__ __launch_bounds__(256, 2)
void sgemm_bias(const float* __restrict__ A, int lda, int aoff,
                const float* __restrict__ W, int ldw,
                const float* __restrict__ bias,
                float* __restrict__ C, int ldc,
                int N, int K)
{
    sgemm_core(A, lda, aoff, W, ldw, bias, C, ldc, N, K);
}

// three up-projections in one launch (blockIdx.z selects q/k/v)
__global__ __launch_bounds__(256, 2)
void sgemm_up3(const float* __restrict__ latent,
               const float* __restrict__ w0, const float* __restrict__ b0, float* __restrict__ c0,
               const float* __restrict__ w1, const float* __restrict__ b1, float* __restrict__ c1,
               const float* __restrict__ w2, const float* __restrict__ b2, float* __restrict__ c2)
{
    const int z = blockIdx.z;
    const float* W  = (z == 0) ? w0 : (z == 1) ? w1 : w2;
    const float* Bb = (z == 0) ? b0 : (z == 1) ? b1 : b2;
    float*       C  = (z == 0) ? c0 : (z == 1) ? c1 : c2;
    sgemm_core(latent, 3 * LAT, z * LAT, W, DMODEL, Bb, C, DMODEL, DMODEL, LAT);
}

// ======================= fused RoPE kernel =================================
#define LOG2_THETA_OVER_32 0.48780126482613787f
#define QROT (MROWS * 512)   // pos_q rotation pairs
#define KROT (MROWS * 32)    // pos_k rotation pairs

__global__ void rope_kernel(float* __restrict__ pq, float* __restrict__ pk)
{
    int idx = blockIdx.x * 256 + threadIdx.x;
    if (idx >= QROT + KROT) return;

    float* base;
    int s, i;
    if (idx < QROT) {
        int r   = idx >> 9;
        int rem = idx & 511;
        int h   = rem >> 5;
        i       = rem & 31;
        s       = r & (SS - 1);
        base = pq + (long)r * (NHD * PHD) + h * PHD + i;
    } else {
        int k = idx - QROT;
        int r = k >> 5;
        i     = k & 31;
        s     = r & (SS - 1);
        base = pk + (long)r * PHD + i;
    }

    float invf = exp2f(-(float)i * LOG2_THETA_OVER_32);
    float ang  = (float)s * invf;
    float sn, cs;
    sincosf(ang, &sn, &cs);

    float x0 = base[0], x1 = base[32];
    base[0]  = x0 * cs - x1 * sn;
    base[32] = x1 * cs + x0 * sn;
}

// ======================= flash attention v3 ================================
// 128x64 tiles. 512 threads: tx 0..15, ty 0..31; each thread 4 q-rows
// (r0=4ty), score cols {tx+16j}; output cols {4tx, 64+4tx}.
// Single-buffered K/V with cp.async pipelined across stages:
//   K(t+1) issued after softmax barrier (covered by P@V),
//   V(t+1) issued after P@V barrier (covered by next score stage).
#define QTILE 128
#define KTILE 64
#define QPAD 196
#define KPAD 196
#define PPAD 68
#define ATTN_SMEM_FLOATS (QTILE * QPAD + KTILE * KPAD + KTILE * 128 + QTILE * PPAD)
#define ATTN_SMEM_BYTES  (ATTN_SMEM_FLOATS * 4)   // 218,112 B

__device__ __forceinline__ void cp_async16(void* smem_dst, const void* gmem_src)
{
    uint32_t dst = (uint32_t)__cvta_generic_to_shared(smem_dst);
    asm volatile("cp.async.cg.shared.global [%0], [%1], 16;\n"
                 :: "r"(dst), "l"(gmem_src));
}

__device__ __forceinline__ void load_k_async(
    const float* __restrict__ kmain, const float* __restrict__ posk,
    long rowbase, int h, int n0, float* Ks, int tid)
{
    // 64 rows x 48 float4-chunks (32 main + 16 pos) = 3072 chunks
#pragma unroll
    for (int j = 0; j < 6; j++) {
        int c   = tid + j * 512;
        int row = c / 48;
        int dc  = c % 48;
        const float* src = (dc < 32)
            ? kmain + (rowbase + n0 + row) * DMODEL + h * HD + dc * 4
            : posk  + (rowbase + n0 + row) * PHD + (dc - 32) * 4;
        cp_async16(Ks + row * KPAD + dc * 4, src);
    }
}

__device__ __forceinline__ void load_v_async(
    const float* __restrict__ vmain,
    long rowbase, int h, int n0, float* Vs, int tid)
{
    // 64 rows x 32 float4-chunks = 2048 chunks
#pragma unroll
    for (int j = 0; j < 4; j++) {
        int c   = tid + j * 512;
        int row = c >> 5;
        int dc  = c & 31;
        cp_async16(Vs + row * 128 + dc * 4,
                   vmain + (rowbase + n0 + row) * DMODEL + h * HD + dc * 4);
    }
}

__global__ __launch_bounds__(512, 1)
void attn_kernel(const float* __restrict__ qmain, const float* __restrict__ posq,
                 const float* __restrict__ kmain, const float* __restrict__ posk,
                 const float* __restrict__ vmain, float* __restrict__ outp)
{
    extern __shared__ float sm[];
    float* Qs = sm;                          // [128][QPAD]
    float* Ks = Qs + QTILE * QPAD;           // [64][KPAD]
    float* Vs = Ks + KTILE * KPAD;           // [64][128]
    float* Ps = Vs + KTILE * 128;            // [128][PPAD]

    const int bh  = blockIdx.y;
    const int b   = bh >> 4;
    const int h   = bh & 15;
    const int qti = (int)gridDim.x - 1 - (int)blockIdx.x;  // heavy tiles first
    const int m0  = qti * QTILE;
    const int nk  = 2 * qti + 2;             // k-tiles covering rows < m0+128

    const int tid = threadIdx.x;
    const int tx  = tid & 15;
    const int ty  = tid >> 4;
    const int r0  = ty * 4;

    const long rowbase = (long)b * SS;
    const float scale = 0.07216878364870323f;  // 1/sqrt(192)

    // ---- prefetch K/V tile 0 and Q tile (all cp.async, one group) ----
    load_k_async(kmain, posk, rowbase, h, 0, Ks, tid);
    load_v_async(vmain, rowbase, h, 0, Vs, tid);
    // Q: 128 rows x 48 float4-chunks = 6144 chunks
#pragma unroll
    for (int j = 0; j < 12; j++) {
        int c   = tid + j * 512;
        int row = c / 48;
        int dc  = c % 48;
        const float* src = (dc < 32)
            ? qmain + (rowbase + m0 + row) * DMODEL + h * HD + dc * 4
            : posq  + (rowbase + m0 + row) * (NHD * PHD) + h * PHD + (dc - 32) * 4;
        cp_async16(Qs + row * QPAD + dc * 4, src);
    }
    asm volatile("cp.async.commit_group;\n" ::: "memory");

    float mi[4], li[4], acc[4][8];
#pragma unroll
    for (int i = 0; i < 4; i++) {
        mi[i] = -1e30f;
        li[i] = 0.0f;
#pragma unroll
        for (int j = 0; j < 8; j++) acc[i][j] = 0.0f;
    }

    for (int t = 0; t < nk; ++t) {
        asm volatile("cp.async.wait_group 0;\n" ::: "memory");
        __syncthreads();   // barrier A: K(t), V(t) (and Q) visible

        const int n0 = t * KTILE;

        // ---- scores: 4 rows x 4 cols per thread over DQK=192 ----
        float sc[4][4];
#pragma unroll
        for (int i = 0; i < 4; i++)
#pragma unroll
            for (int j = 0; j < 4; j++) sc[i][j] = 0.0f;

#pragma unroll 2
        for (int k4 = 0; k4 < DQK; k4 += 4) {
            float4 qv[4], kv[4];
#pragma unroll
            for (int i = 0; i < 4; i++)
                qv[i] = *(const float4*)&Qs[(r0 + i) * QPAD + k4];
#pragma unroll
            for (int j = 0; j < 4; j++)
                kv[j] = *(const float4*)&Ks[(tx + 16 * j) * KPAD + k4];
#pragma unroll
            for (int i = 0; i < 4; i++)
#pragma unroll
                for (int j = 0; j < 4; j++) {
                    sc[i][j] = fmaf(qv[i].x, kv[j].x, sc[i][j]);
                    sc[i][j] = fmaf(qv[i].y, kv[j].y, sc[i][j]);
                    sc[i][j] = fmaf(qv[i].z, kv[j].z, sc[i][j]);
                    sc[i][j] = fmaf(qv[i].w, kv[j].w, sc[i][j]);
                }
        }

        // scale + causal mask (only the last two k-tiles touch the diagonal)
        const bool diag = (t >= 2 * qti);
#pragma unroll
        for (int i = 0; i < 4; i++)
#pragma unroll
            for (int j = 0; j < 4; j++) {
                sc[i][j] *= scale;
                if (diag) {
                    int nq = n0 + tx + 16 * j;
                    int mq = m0 + r0 + i;
                    if (nq > mq) sc[i][j] = -1e30f;
                }
            }

        // ---- online softmax update (per row, reduced across 16 tx lanes) --
#pragma unroll
        for (int i = 0; i < 4; i++) {
            float tmax = fmaxf(fmaxf(sc[i][0], sc[i][1]), fmaxf(sc[i][2], sc[i][3]));
#pragma unroll
            for (int off = 8; off >= 1; off >>= 1)
                tmax = fmaxf(tmax, __shfl_xor_sync(0xffffffffu, tmax, off));

            float mnew  = fmaxf(mi[i], tmax);
            float alpha = __expf(mi[i] - mnew);

            float ps0 = __expf(sc[i][0] - mnew);
            float ps1 = __expf(sc[i][1] - mnew);
            float ps2 = __expf(sc[i][2] - mnew);
            float ps3 = __expf(sc[i][3] - mnew);
            float rsum = ps0 + ps1 + ps2 + ps3;
#pragma unroll
            for (int off = 8; off >= 1; off >>= 1)
                rsum += __shfl_xor_sync(0xffffffffu, rsum, off);

            li[i] = li[i] * alpha + rsum;
            mi[i] = mnew;
#pragma unroll
            for (int d = 0; d < 8; d++) acc[i][d] *= alpha;

            Ps[(r0 + i) * PPAD + tx]      = ps0;
            Ps[(r0 + i) * PPAD + tx + 16] = ps1;
            Ps[(r0 + i) * PPAD + tx + 32] = ps2;
            Ps[(r0 + i) * PPAD + tx + 48] = ps3;
        }
        __syncthreads();   // barrier B: Ps ready; all K reads done

        // prefetch K(t+1) — overlaps with P@V below
        if (t + 1 < nk) {
            load_k_async(kmain, posk, rowbase, h, (t + 1) * KTILE, Ks, tid);
            asm volatile("cp.async.commit_group;\n" ::: "memory");
        }

        // ---- P @ V : each thread 4 rows x 8 d-cols (split 4+4) ----
#pragma unroll 2
        for (int n = 0; n < KTILE; n++) {
            float4 v0 = *(const float4*)&Vs[n * 128 + tx * 4];
            float4 v1 = *(const float4*)&Vs[n * 128 + 64 + tx * 4];
#pragma unroll
            for (int i = 0; i < 4; i++) {
                float p = Ps[(r0 + i) * PPAD + n];
                acc[i][0] = fmaf(p, v0.x, acc[i][0]);
                acc[i][1] = fmaf(p, v0.y, acc[i][1]);
                acc[i][2] = fmaf(p, v0.z, acc[i][2]);
                acc[i][3] = fmaf(p, v0.w, acc[i][3]);
                acc[i][4] = fmaf(p, v1.x, acc[i][4]);
                acc[i][5] = fmaf(p, v1.y, acc[i][5]);
                acc[i][6] = fmaf(p, v1.z, acc[i][6]);
                acc[i][7] = fmaf(p, v1.w, acc[i][7]);
            }
        }
        __syncthreads();   // barrier C: all V (and Ps) reads done

        // prefetch V(t+1) — overlaps with next score stage
        if (t + 1 < nk) {
            load_v_async(vmain, rowbase, h, (t + 1) * KTILE, Vs, tid);
            asm volatile("cp.async.commit_group;\n" ::: "memory");
        }
    }

    // ---- write O, packed as [b, s, h, d] ----
#pragma unroll
    for (int i = 0; i < 4; i++) {
        float inv = 1.0f / li[i];
        long row = rowbase + m0 + r0 + i;
        float4 o0 = make_float4(acc[i][0] * inv, acc[i][1] * inv,
                                acc[i][2] * inv, acc[i][3] * inv);
        float4 o1 = make_float4(acc[i][4] * inv, acc[i][5] * inv,
                                acc[i][6] * inv, acc[i][7] * inv);
        *(float4*)&outp[row * DMODEL + h * HD + tx * 4]      = o0;
        *(float4*)&outp[row * DMODEL + h * HD + 64 + tx * 4] = o1;
    }
}

// ======================= launch ============================================
extern "C" void kernel_launch(void* const* d_in, const int* in_sizes, int n_in,
                              void* d_out, int out_size)
{
    const float* x      = (const float*)d_in[0];
    const float* w_qkv  = (const float*)d_in[1];
    const float* b_qkv  = (const float*)d_in[2];
    const float* w_qup  = (const float*)d_in[3];
    const float* b_qup  = (const float*)d_in[4];
    const float* w_kup  = (const float*)d_in[5];
    const float* b_kup  = (const float*)d_in[6];
    const float* w_vup  = (const float*)d_in[7];
    const float* b_vup  = (const float*)d_in[8];
    const float* w_qpos = (const float*)d_in[9];
    const float* b_qpos = (const float*)d_in[10];
    const float* w_kpos = (const float*)d_in[11];
    const float* b_kpos = (const float*)d_in[12];
    const float* w_o    = (const float*)d_in[13];
    const float* b_o    = (const float*)d_in[14];
    float* out = (float*)d_out;

    float *latent, *qmain, *kmain, *vmain, *posq, *posk, *attnb;
    cudaGetSymbolAddress((void**)&latent, g_latent);
    cudaGetSymbolAddress((void**)&qmain,  g_qmain);
    cudaGetSymbolAddress((void**)&kmain,  g_kmain);
    cudaGetSymbolAddress((void**)&vmain,  g_vmain);
    cudaGetSymbolAddress((void**)&posq,   g_posq);
    cudaGetSymbolAddress((void**)&posk,   g_posk);
    cudaGetSymbolAddress((void**)&attnb,  g_attn);

    cudaFuncSetAttribute(attn_kernel,
                         cudaFuncAttributeMaxDynamicSharedMemorySize,
                         ATTN_SMEM_BYTES);

    dim3 blk(256);
    const int MG = MROWS / 128;  // 32 grid rows

    // 1) latent_qkv = x @ w_qkv + b_qkv             [4096,1536]
    sgemm_bias<<<dim3(1536 / 128, MG), blk>>>(x, DMODEL, 0, w_qkv, 3 * LAT,
                                              b_qkv, latent, 3 * LAT,
                                              3 * LAT, DMODEL);
    // 2) pos_k raw = x @ w_kpos + b_kpos            [4096,64]
    sgemm_bias<<<dim3(1, MG), blk>>>(x, DMODEL, 0, w_kpos, PHD,
                                     b_kpos, posk, PHD, PHD, DMODEL);
    // 3) q/k/v up-projections in one launch         3 x [4096,2048]
    sgemm_up3<<<dim3(DMODEL / 128, MG, 3), blk>>>(latent,
                                                  w_qup, b_qup, qmain,
                                                  w_kup, b_kup, kmain,
                                                  w_vup, b_vup, vmain);
    // 4) pos_q raw = lq @ w_qpos + b_qpos           [4096,1024]
    sgemm_bias<<<dim3(1024 / 128, MG), blk>>>(latent, 3 * LAT, 0, w_qpos, NHD * PHD,
                                              b_qpos, posq, NHD * PHD, NHD * PHD, LAT);
    // 5) RoPE (in place, fused q+k)
    rope_kernel<<<(QROT + KROT + 255) / 256, 256>>>(posq, posk);

    // 6) attention -> attnb packed [b, s, h, d]
    attn_kernel<<<dim3(SS / QTILE, BB * NHD), dim3(512), ATTN_SMEM_BYTES>>>(
        qmain, posq, kmain, posk, vmain, attnb);

    // 7) out = attnb @ w_o + b_o                    [4096,2048]
    sgemm_bias<<<dim3(DMODEL / 128, MG), blk>>>(attnb, DMODEL, 0, w_o, DMODEL,
                                                b_o, out, DMODEL, DMODEL, DMODEL);
}

// round 11
// speedup vs baseline: 1.4491x; 1.4491x over previous
#include <cuda_runtime.h>
#include <cuda_bf16.h>
#include <math.h>
#include <stdint.h>

#define BB     2
#define SS     2048
#define DMODEL 2048
#define LAT    512
#define NHD    16
#define HD     128
#define PHD    64
#define DQK    192
#define MROWS  4096

// ---------------- fp32 scratch ----------------
__device__ float g_latent[MROWS * 1536];
__device__ float g_qmain [MROWS * DMODEL];
__device__ float g_kmain [MROWS * DMODEL];
__device__ float g_vmain [MROWS * DMODEL];
__device__ float g_posq  [MROWS * 1024];
__device__ float g_posk  [MROWS * 128];    // padded to 128 cols
__device__ float g_attn  [MROWS * DMODEL];
__device__ float g_bk128 [128];

// ---------------- bf16 split operands ----------------
__device__ __nv_bfloat16 g_xh[MROWS*DMODEL], g_xl[MROWS*DMODEL];
__device__ __nv_bfloat16 g_lh[MROWS*1536],   g_ll[MROWS*1536];
__device__ __nv_bfloat16 g_abh[MROWS*DMODEL],g_abl[MROWS*DMODEL];
__device__ __nv_bfloat16 g_wqkvh[1536*2048], g_wqkvl[1536*2048];
__device__ __nv_bfloat16 g_wkph[128*2048],   g_wkpl[128*2048];
__device__ __nv_bfloat16 g_wquh[2048*512],   g_wqul[2048*512];
__device__ __nv_bfloat16 g_wkuh[2048*512],   g_wkul[2048*512];
__device__ __nv_bfloat16 g_wvuh[2048*512],   g_wvul[2048*512];
__device__ __nv_bfloat16 g_wqph[1024*512],   g_wqpl[1024*512];
__device__ __nv_bfloat16 g_woh[2048*2048],   g_wol[2048*2048];

// ======================= helpers ===========================================
__device__ __forceinline__ uint32_t s2u(const void* p) {
    return (uint32_t)__cvta_generic_to_shared(const_cast<void*>(p));
}
__device__ __forceinline__ void cp16(void* d, const void* s) {
    asm volatile("cp.async.cg.shared.global [%0],[%1],16;\n"
                 :: "r"(s2u(d)), "l"(s) : "memory");
}
__device__ __forceinline__ void ldsm_x4(uint32_t* r, uint32_t addr) {
    asm volatile("ldmatrix.sync.aligned.m8n8.x4.shared.b16 {%0,%1,%2,%3},[%4];"
                 : "=r"(r[0]), "=r"(r[1]), "=r"(r[2]), "=r"(r[3]) : "r"(addr));
}
__device__ __forceinline__ void mma_bf16(float* d, const uint32_t* a,
                                         uint32_t b0, uint32_t b1) {
    asm volatile(
        "mma.sync.aligned.m16n8k16.row.col.f32.bf16.bf16.f32 "
        "{%0,%1,%2,%3},{%4,%5,%6,%7},{%8,%9},{%0,%1,%2,%3};"
        : "+f"(d[0]), "+f"(d[1]), "+f"(d[2]), "+f"(d[3])
        : "r"(a[0]), "r"(a[1]), "r"(a[2]), "r"(a[3]), "r"(b0), "r"(b1));
}

// ======================= mma.sync bf16-split GEMM ==========================
// C[m,n] = sum_k A[m*lda+aoff+k]*W[k,n] + bias[n]; WT pre-transposed [N][K].
// CTA tile 128x128, 8 warps (warp tile 64x32), K-chunks of 64 bf16.
// SMEM stage: Ah/Al/Bh/Bl 128x64 bf16 each (128B rows, SW128 swizzle).
#define TGSTG  65536
#define TG_SMEM (2 * TGSTG)

__device__ __forceinline__ void tg_load(
    const __nv_bfloat16* ah, const __nv_bfloat16* al,
    const __nv_bfloat16* bh, const __nv_bfloat16* bl,
    long m0, long n0, int lda, int aoff, int ldb, int kc, char* buf, int tid)
{
#pragma unroll
    for (int t4 = 0; t4 < 4; t4++) {
        const __nv_bfloat16* base = t4 == 0 ? ah : t4 == 1 ? al : t4 == 2 ? bh : bl;
        long r0 = (t4 < 2) ? m0 : n0;
        long ld = (t4 < 2) ? lda : ldb;
        int  o0 = ((t4 < 2) ? aoff : 0) + kc;
#pragma unroll
        for (int i = 0; i < 4; i++) {
            int v = tid + i * 256;
            int row = v >> 3, c16 = v & 7;
            uint32_t byte = row * 128 + c16 * 16;
            uint32_t sw = byte ^ ((byte >> 3) & 0x70);
            cp16(buf + t4 * 16384 + sw, base + (r0 + row) * ld + o0 + c16 * 8);
        }
    }
}

__global__ __launch_bounds__(256, 1)
void tgemm(const __nv_bfloat16* __restrict__ ah, const __nv_bfloat16* __restrict__ al,
           int lda, int aoff,
           const __nv_bfloat16* __restrict__ bth, const __nv_bfloat16* __restrict__ btl,
           const float* __restrict__ bias, float* __restrict__ C, int ldc, int K)
{
    extern __shared__ char smb[];
    const int tid = threadIdx.x, wid = tid >> 5, lane = tid & 31;
    const long m0 = blockIdx.y * 128L, n0 = blockIdx.x * 128L;
    const int wm = wid & 1;        // 0..1 -> 64-row half
    const int wn = wid >> 1;       // 0..3 -> 32-col quarter

    float acc[16][4];
#pragma unroll
    for (int i = 0; i < 16; i++)
#pragma unroll
        for (int j = 0; j < 4; j++) acc[i][j] = 0.0f;

    const int nch = K >> 6;
    tg_load(ah, al, bth, btl, m0, n0, lda, aoff, K, 0, smb, tid);
    asm volatile("cp.async.commit_group;\n" ::: "memory");

    // per-thread ldmatrix address components (constant across chunks)
    const int a_lrow = lane & 15;                       // A line within atom
    const int a_koff = (lane >> 4) * 16;                // A 16B k-block
    const int b_lrow = (lane & 7) + ((lane >> 4) << 3); // B n-line
    const int b_koff = ((lane >> 3) & 1) << 4;          // B 16B k-block

    for (int c = 0; c < nch; c++) {
        if (c + 1 < nch) {
            tg_load(ah, al, bth, btl, m0, n0, lda, aoff, K, (c + 1) * 64,
                    smb + ((c + 1) & 1) * TGSTG, tid);
            asm volatile("cp.async.commit_group;\n" ::: "memory");
            asm volatile("cp.async.wait_group 1;\n" ::: "memory");
        } else {
            asm volatile("cp.async.wait_group 0;\n" ::: "memory");
        }
        __syncthreads();   // stage c visible

        const uint32_t sb = s2u(smb + (c & 1) * TGSTG);

#pragma unroll
        for (int ks = 0; ks < 4; ks++) {
            uint32_t afh[4][4], afl[4][4], bfh[2][4], bfl[2][4];
            const int akb = ks * 32 + a_koff;
#pragma unroll
            for (int im = 0; im < 4; im++) {
                int row = wm * 64 + im * 16 + a_lrow;
                uint32_t off = row * 128 + (akb ^ ((row & 7) << 4));
                ldsm_x4(afh[im], sb + off);
                ldsm_x4(afl[im], sb + 16384 + off);
            }
            const int bkb = ks * 32 + b_koff;
#pragma unroll
            for (int inp = 0; inp < 2; inp++) {
                int row = wn * 32 + inp * 16 + b_lrow;
                uint32_t off = row * 128 + (bkb ^ ((row & 7) << 4));
                ldsm_x4(bfh[inp], sb + 32768 + off);
                ldsm_x4(bfl[inp], sb + 49152 + off);
            }
#pragma unroll
            for (int im = 0; im < 4; im++)
#pragma unroll
                for (int in_ = 0; in_ < 4; in_++) {
                    uint32_t h0 = bfh[in_ >> 1][(in_ & 1) * 2];
                    uint32_t h1 = bfh[in_ >> 1][(in_ & 1) * 2 + 1];
                    uint32_t l0 = bfl[in_ >> 1][(in_ & 1) * 2];
                    uint32_t l1 = bfl[in_ >> 1][(in_ & 1) * 2 + 1];
                    float* d = acc[im * 4 + in_];
                    mma_bf16(d, afh[im], h0, h1);   // Ah*Bh
                    mma_bf16(d, afh[im], l0, l1);   // Ah*Bl
                    mma_bf16(d, afl[im], h0, h1);   // Al*Bh
                }
        }
        __syncthreads();   // all reads of stage (c&1) done before reuse
    }

    // ---- epilogue: bias + store ----
    const long mb = m0 + wm * 64 + (lane >> 2);
    const int  nb = (int)n0 + wn * 32 + (lane & 3) * 2;
#pragma unroll
    for (int im = 0; im < 4; im++) {
#pragma unroll
        for (int in_ = 0; in_ < 4; in_++) {
            const float* d = acc[im * 4 + in_];
            int col = nb + in_ * 8;
            float2 bv = *(const float2*)&bias[col];
            long r1 = mb + im * 16;
            *(float2*)&C[r1 * (long)ldc + col] =
                make_float2(d[0] + bv.x, d[1] + bv.y);
            *(float2*)&C[(r1 + 8) * (long)ldc + col] =
                make_float2(d[2] + bv.x, d[3] + bv.y);
        }
    }
}

// ======================= conversion kernels ================================
__global__ void split_f32(const float* __restrict__ s, __nv_bfloat16* __restrict__ h,
                          __nv_bfloat16* __restrict__ l, int n)
{
    int i = blockIdx.x * 256 + threadIdx.x;
    if (i >= n) return;
    float v = s[i];
    __nv_bfloat16 hv = __float2bfloat16(v);
    h[i] = hv;
    l[i] = __float2bfloat16(v - __bfloat162float(hv));
}

// W [K][N] -> WT hi/lo [Npad][K]; grid (Npad/32, K/32), block (32,8)
__global__ void tsplit(const float* __restrict__ w, __nv_bfloat16* __restrict__ th,
                       __nv_bfloat16* __restrict__ tl, int K, int N)
{
    __shared__ float t[32][33];
    int nb = blockIdx.x * 32, kb = blockIdx.y * 32;
    for (int r = threadIdx.y; r < 32; r += 8) {
        int n = nb + threadIdx.x;
        t[r][threadIdx.x] = (n < N) ? w[(long)(kb + r) * N + n] : 0.0f;
    }
    __syncthreads();
    for (int r = threadIdx.y; r < 32; r += 8) {
        long n = nb + r, k = kb + threadIdx.x;
        float v = t[threadIdx.x][r];
        __nv_bfloat16 hv = __float2bfloat16(v);
        th[n * K + k] = hv;
        tl[n * K + k] = __float2bfloat16(v - __bfloat162float(hv));
    }
}

__global__ void pad64(const float* __restrict__ b, float* __restrict__ o)
{
    int i = threadIdx.x;
    o[i] = (i < 64) ? b[i] : 0.0f;
}

// ======================= fused RoPE ========================================
#define LOG2_THETA_OVER_32 0.48780126482613787f
#define QROT (MROWS * 512)
#define KROT (MROWS * 32)

__global__ void rope_kernel(float* __restrict__ pq, float* __restrict__ pk)
{
    int idx = blockIdx.x * 256 + threadIdx.x;
    if (idx >= QROT + KROT) return;
    float* base; int s, i;
    if (idx < QROT) {
        int r = idx >> 9, rem = idx & 511, h = rem >> 5;
        i = rem & 31; s = r & (SS - 1);
        base = pq + (long)r * 1024 + h * PHD + i;
    } else {
        int k = idx - QROT, r = k >> 5;
        i = k & 31; s = r & (SS - 1);
        base = pk + (long)r * 128 + i;
    }
    float ang = (float)s * exp2f(-(float)i * LOG2_THETA_OVER_32);
    float sn, cs; sincosf(ang, &sn, &cs);
    float x0 = base[0], x1 = base[32];
    base[0]  = x0 * cs - x1 * sn;
    base[32] = x1 * cs + x0 * sn;
}

// ======================= flash attention ===================================
#define QTILE 128
#define KTILE 64
#define QPAD 196
#define KPAD 196
#define PPAD 68
#define ATTN_SMEM_FLOATS (QTILE*QPAD + KTILE*KPAD + KTILE*128 + QTILE*PPAD)
#define ATTN_SMEM_BYTES  (ATTN_SMEM_FLOATS * 4)

__device__ __forceinline__ void load_k_async(
    const float* __restrict__ kmain, const float* __restrict__ posk,
    long rowbase, int h, int n0, float* Ks, int tid)
{
#pragma unroll
    for (int j = 0; j < 6; j++) {
        int c = tid + j * 512, row = c / 48, dc = c % 48;
        const float* src = (dc < 32)
            ? kmain + (rowbase + n0 + row) * DMODEL + h * HD + dc * 4
            : posk  + (rowbase + n0 + row) * 128 + (dc - 32) * 4;
        cp16(Ks + row * KPAD + dc * 4, src);
    }
}
__device__ __forceinline__ void load_v_async(
    const float* __restrict__ vmain, long rowbase, int h, int n0, float* Vs, int tid)
{
#pragma unroll
    for (int j = 0; j < 4; j++) {
        int c = tid + j * 512, row = c >> 5, dc = c & 31;
        cp16(Vs + row * 128 + dc * 4,
             vmain + (rowbase + n0 + row) * DMODEL + h * HD + dc * 4);
    }
}

__global__ __launch_bounds__(512, 1)
void attn_kernel(const float* __restrict__ qmain, const float* __restrict__ posq,
                 const float* __restrict__ kmain, const float* __restrict__ posk,
                 const float* __restrict__ vmain, float* __restrict__ outp)
{
    extern __shared__ float sm[];
    float* Qs = sm;
    float* Ks = Qs + QTILE * QPAD;
    float* Vs = Ks + KTILE * KPAD;
    float* Ps = Vs + KTILE * 128;

    const int bh = blockIdx.y, b = bh >> 4, h = bh & 15;
    const int qti = (int)gridDim.x - 1 - (int)blockIdx.x;
    const int m0 = qti * QTILE, nk = 2 * qti + 2;
    const int tid = threadIdx.x, tx = tid & 15, ty = tid >> 4, r0 = ty * 4;
    const long rowbase = (long)b * SS;
    const float scale = 0.07216878364870323f;

    load_k_async(kmain, posk, rowbase, h, 0, Ks, tid);
    load_v_async(vmain, rowbase, h, 0, Vs, tid);
#pragma unroll
    for (int j = 0; j < 12; j++) {
        int c = tid + j * 512, row = c / 48, dc = c % 48;
        const float* src = (dc < 32)
            ? qmain + (rowbase + m0 + row) * DMODEL + h * HD + dc * 4
            : posq  + (rowbase + m0 + row) * 1024 + h * PHD + (dc - 32) * 4;
        cp16(Qs + row * QPAD + dc * 4, src);
    }
    asm volatile("cp.async.commit_group;\n" ::: "memory");

    float mi[4], li[4], acc[4][8];
#pragma unroll
    for (int i = 0; i < 4; i++) {
        mi[i] = -1e30f; li[i] = 0.0f;
#pragma unroll
        for (int j = 0; j < 8; j++) acc[i][j] = 0.0f;
    }

    for (int t = 0; t < nk; ++t) {
        asm volatile("cp.async.wait_group 0;\n" ::: "memory");
        __syncthreads();
        const int n0 = t * KTILE;

        float sc[4][4];
#pragma unroll
        for (int i = 0; i < 4; i++)
#pragma unroll
            for (int j = 0; j < 4; j++) sc[i][j] = 0.0f;

#pragma unroll 2
        for (int k4 = 0; k4 < DQK; k4 += 4) {
            float4 qv[4], kv[4];
#pragma unroll
            for (int i = 0; i < 4; i++)
                qv[i] = *(const float4*)&Qs[(r0 + i) * QPAD + k4];
#pragma unroll
            for (int j = 0; j < 4; j++)
                kv[j] = *(const float4*)&Ks[(tx + 16 * j) * KPAD + k4];
#pragma unroll
            for (int i = 0; i < 4; i++)
#pragma unroll
                for (int j = 0; j < 4; j++) {
                    sc[i][j] = fmaf(qv[i].x, kv[j].x, sc[i][j]);
                    sc[i][j] = fmaf(qv[i].y, kv[j].y, sc[i][j]);
                    sc[i][j] = fmaf(qv[i].z, kv[j].z, sc[i][j]);
                    sc[i][j] = fmaf(qv[i].w, kv[j].w, sc[i][j]);
                }
        }

        const bool diag = (t >= 2 * qti);
#pragma unroll
        for (int i = 0; i < 4; i++)
#pragma unroll
            for (int j = 0; j < 4; j++) {
                sc[i][j] *= scale;
                if (diag && (n0 + tx + 16 * j) > (m0 + r0 + i)) sc[i][j] = -1e30f;
            }

#pragma unroll
        for (int i = 0; i < 4; i++) {
            float tmax = fmaxf(fmaxf(sc[i][0], sc[i][1]), fmaxf(sc[i][2], sc[i][3]));
#pragma unroll
            for (int off = 8; off >= 1; off >>= 1)
                tmax = fmaxf(tmax, __shfl_xor_sync(0xffffffffu, tmax, off));
            float mnew = fmaxf(mi[i], tmax);
            float alpha = __expf(mi[i] - mnew);
            float ps0 = __expf(sc[i][0] - mnew), ps1 = __expf(sc[i][1] - mnew);
            float ps2 = __expf(sc[i][2] - mnew), ps3 = __expf(sc[i][3] - mnew);
            float rsum = ps0 + ps1 + ps2 + ps3;
#pragma unroll
            for (int off = 8; off >= 1; off >>= 1)
                rsum += __shfl_xor_sync(0xffffffffu, rsum, off);
            li[i] = li[i] * alpha + rsum;
            mi[i] = mnew;
#pragma unroll
            for (int d = 0; d < 8; d++) acc[i][d] *= alpha;
            Ps[(r0 + i) * PPAD + tx]      = ps0;
            Ps[(r0 + i) * PPAD + tx + 16] = ps1;
            Ps[(r0 + i) * PPAD + tx + 32] = ps2;
            Ps[(r0 + i) * PPAD + tx + 48] = ps3;
        }
        __syncthreads();

        if (t + 1 < nk) {
            load_k_async(kmain, posk, rowbase, h, (t + 1) * KTILE, Ks, tid);
            asm volatile("cp.async.commit_group;\n" ::: "memory");
        }

#pragma unroll 2
        for (int n = 0; n < KTILE; n++) {
            float4 v0 = *(const float4*)&Vs[n * 128 + tx * 4];
            float4 v1 = *(const float4*)&Vs[n * 128 + 64 + tx * 4];
#pragma unroll
            for (int i = 0; i < 4; i++) {
                float p = Ps[(r0 + i) * PPAD + n];
                acc[i][0] = fmaf(p, v0.x, acc[i][0]);
                acc[i][1] = fmaf(p, v0.y, acc[i][1]);
                acc[i][2] = fmaf(p, v0.z, acc[i][2]);
                acc[i][3] = fmaf(p, v0.w, acc[i][3]);
                acc[i][4] = fmaf(p, v1.x, acc[i][4]);
                acc[i][5] = fmaf(p, v1.y, acc[i][5]);
                acc[i][6] = fmaf(p, v1.z, acc[i][6]);
                acc[i][7] = fmaf(p, v1.w, acc[i][7]);
            }
        }
        __syncthreads();

        if (t + 1 < nk) {
            load_v_async(vmain, rowbase, h, (t + 1) * KTILE, Vs, tid);
            asm volatile("cp.async.commit_group;\n" ::: "memory");
        }
    }

#pragma unroll
    for (int i = 0; i < 4; i++) {
        float inv = 1.0f / li[i];
        long row = rowbase + m0 + r0 + i;
        float4 o0 = make_float4(acc[i][0]*inv, acc[i][1]*inv, acc[i][2]*inv, acc[i][3]*inv);
        float4 o1 = make_float4(acc[i][4]*inv, acc[i][5]*inv, acc[i][6]*inv, acc[i][7]*inv);
        *(float4*)&outp[row * DMODEL + h * HD + tx * 4]      = o0;
        *(float4*)&outp[row * DMODEL + h * HD + 64 + tx * 4] = o1;
    }
}

// ======================= launch ============================================
#define SYM(p, s) cudaGetSymbolAddress((void**)&p, s)

extern "C" void kernel_launch(void* const* d_in, const int* in_sizes, int n_in,
                              void* d_out, int out_size)
{
    const float* x      = (const float*)d_in[0];
    const float* w_qkv  = (const float*)d_in[1];
    const float* b_qkv  = (const float*)d_in[2];
    const float* w_qup  = (const float*)d_in[3];
    const float* b_qup  = (const float*)d_in[4];
    const float* w_kup  = (const float*)d_in[5];
    const float* b_kup  = (const float*)d_in[6];
    const float* w_vup  = (const float*)d_in[7];
    const float* b_vup  = (const float*)d_in[8];
    const float* w_qpos = (const float*)d_in[9];
    const float* b_qpos = (const float*)d_in[10];
    const float* w_kpos = (const float*)d_in[11];
    const float* b_kpos = (const float*)d_in[12];
    const float* w_o    = (const float*)d_in[13];
    const float* b_o    = (const float*)d_in[14];
    float* out = (float*)d_out;

    float *latent, *qmain, *kmain, *vmain, *posq, *posk, *attnb, *bk128;
    SYM(latent, g_latent); SYM(qmain, g_qmain); SYM(kmain, g_kmain);
    SYM(vmain, g_vmain);   SYM(posq, g_posq);   SYM(posk, g_posk);
    SYM(attnb, g_attn);    SYM(bk128, g_bk128);
    __nv_bfloat16 *xh,*xl,*lh,*ll,*abh,*abl,*wqkvh,*wqkvl,*wkph,*wkpl,
                  *wquh,*wqul,*wkuh,*wkul,*wvuh,*wvul,*wqph,*wqpl,*woh,*wol;
    SYM(xh,g_xh); SYM(xl,g_xl); SYM(lh,g_lh); SYM(ll,g_ll);
    SYM(abh,g_abh); SYM(abl,g_abl);
    SYM(wqkvh,g_wqkvh); SYM(wqkvl,g_wqkvl); SYM(wkph,g_wkph); SYM(wkpl,g_wkpl);
    SYM(wquh,g_wquh); SYM(wqul,g_wqul); SYM(wkuh,g_wkuh); SYM(wkul,g_wkul);
    SYM(wvuh,g_wvuh); SYM(wvul,g_wvul); SYM(wqph,g_wqph); SYM(wqpl,g_wqpl);
    SYM(woh,g_woh); SYM(wol,g_wol);

    cudaFuncSetAttribute(tgemm, cudaFuncAttributeMaxDynamicSharedMemorySize, TG_SMEM);
    cudaFuncSetAttribute(attn_kernel, cudaFuncAttributeMaxDynamicSharedMemorySize,
                         ATTN_SMEM_BYTES);
    dim3 t8(32, 8);

    // 1) split x
    split_f32<<<(MROWS * DMODEL) / 256, 256>>>(x, xh, xl, MROWS * DMODEL);
    // 2-3) weight transposes for stage 1
    tsplit<<<dim3(1536 / 32, 2048 / 32), t8>>>(w_qkv, wqkvh, wqkvl, 2048, 1536);
    tsplit<<<dim3(128 / 32, 2048 / 32), t8>>>(w_kpos, wkph, wkpl, 2048, PHD);
    // 4) padded kpos bias
    pad64<<<1, 128>>>(b_kpos, bk128);
    // 5) posk = x @ w_kpos (padded N=128)
    tgemm<<<dim3(1, 32), 256, TG_SMEM>>>(xh, xl, DMODEL, 0, wkph, wkpl,
                                         bk128, posk, 128, DMODEL);
    // 6) latent = x @ w_qkv   [profiled launch]
    tgemm<<<dim3(12, 32), 256, TG_SMEM>>>(xh, xl, DMODEL, 0, wqkvh, wqkvl,
                                          b_qkv, latent, 1536, DMODEL);
    // 7) split latent
    split_f32<<<(MROWS * 1536) / 256, 256>>>(latent, lh, ll, MROWS * 1536);
    // 8-11) up-proj weight transposes
    tsplit<<<dim3(2048 / 32, 512 / 32), t8>>>(w_qup, wquh, wqul, 512, 2048);
    tsplit<<<dim3(2048 / 32, 512 / 32), t8>>>(w_kup, wkuh, wkul, 512, 2048);
    tsplit<<<dim3(2048 / 32, 512 / 32), t8>>>(w_vup, wvuh, wvul, 512, 2048);
    tsplit<<<dim3(1024 / 32, 512 / 32), t8>>>(w_qpos, wqph, wqpl, 512, 1024);
    // 12-15) up-projections
    tgemm<<<dim3(16, 32), 256, TG_SMEM>>>(lh, ll, 1536, 0,    wquh, wqul, b_qup,  qmain, DMODEL, LAT);
    tgemm<<<dim3(16, 32), 256, TG_SMEM>>>(lh, ll, 1536, 512,  wkuh, wkul, b_kup,  kmain, DMODEL, LAT);
    tgemm<<<dim3(16, 32), 256, TG_SMEM>>>(lh, ll, 1536, 1024, wvuh, wvul, b_vup,  vmain, DMODEL, LAT);
    tgemm<<<dim3(8, 32), 256, TG_SMEM>>>(lh, ll, 1536, 0,     wqph, wqpl, b_qpos, posq,  1024,   LAT);
    // 16) RoPE
    rope_kernel<<<(QROT + KROT + 255) / 256, 256>>>(posq, posk);
    // 17) attention
    attn_kernel<<<dim3(SS / QTILE, BB * NHD), dim3(512), ATTN_SMEM_BYTES>>>(
        qmain, posq, kmain, posk, vmain, attnb);
    // 18-19) split attnb + w_o transpose
    split_f32<<<(MROWS * DMODEL) / 256, 256>>>(attnb, abh, abl, MROWS * DMODEL);
    tsplit<<<dim3(2048 / 32, 2048 / 32), t8>>>(w_o, woh, wol, 2048, 2048);
    // 20) out = attnb @ w_o
    tgemm<<<dim3(16, 32), 256, TG_SMEM>>>(abh, abl, DMODEL, 0, woh, wol,
                                          b_o, out, DMODEL, DMODEL);
}

// round 12
// speedup vs baseline: 2.4543x; 1.6936x over previous
#include <cuda_runtime.h>
#include <cuda_bf16.h>
#include <math.h>
#include <stdint.h>

#define BB     2
#define SS     2048
#define DMODEL 2048
#define LAT    512
#define NHD    16
#define HD     128
#define PHD    64
#define DQK    192
#define MROWS  4096

// ---------------- fp32 scratch ----------------
__device__ float g_latent[MROWS * 1536];
__device__ float g_qmain [MROWS * DMODEL];
__device__ float g_kmain [MROWS * DMODEL];
__device__ float g_vmain [MROWS * DMODEL];
__device__ float g_posq  [MROWS * 1024];
__device__ float g_posk  [MROWS * 128];
__device__ float g_attn  [MROWS * DMODEL];
__device__ float g_bk128 [128];

// ---------------- bf16 split operands ----------------
__device__ __nv_bfloat16 g_xh[MROWS*DMODEL], g_xl[MROWS*DMODEL];
__device__ __nv_bfloat16 g_lh[MROWS*1536],   g_ll[MROWS*1536];
__device__ __nv_bfloat16 g_abh[MROWS*DMODEL],g_abl[MROWS*DMODEL];
__device__ __nv_bfloat16 g_wqkvh[1536*2048], g_wqkvl[1536*2048];
__device__ __nv_bfloat16 g_wkph[128*2048],   g_wkpl[128*2048];
__device__ __nv_bfloat16 g_wquh[2048*512],   g_wqul[2048*512];
__device__ __nv_bfloat16 g_wkuh[2048*512],   g_wkul[2048*512];
__device__ __nv_bfloat16 g_wvuh[2048*512],   g_wvul[2048*512];
__device__ __nv_bfloat16 g_wqph[1024*512],   g_wqpl[1024*512];
__device__ __nv_bfloat16 g_woh[2048*2048],   g_wol[2048*2048];
// attention operands
__device__ __nv_bfloat16 g_qch[MROWS*16*192], g_qcl[MROWS*16*192];
__device__ __nv_bfloat16 g_kch[MROWS*16*192], g_kcl[MROWS*16*192];
__device__ __nv_bfloat16 g_vth[2048*MROWS],   g_vtl[2048*MROWS];

// ======================= helpers ===========================================
__device__ __forceinline__ uint32_t s2u(const void* p) {
    return (uint32_t)__cvta_generic_to_shared(const_cast<void*>(p));
}
__device__ __forceinline__ void cp16(void* d, const void* s) {
    asm volatile("cp.async.cg.shared.global [%0],[%1],16;\n"
                 :: "r"(s2u(d)), "l"(s) : "memory");
}
__device__ __forceinline__ void ldsm_x4(uint32_t* r, uint32_t addr) {
    asm volatile("ldmatrix.sync.aligned.m8n8.x4.shared.b16 {%0,%1,%2,%3},[%4];"
                 : "=r"(r[0]), "=r"(r[1]), "=r"(r[2]), "=r"(r[3]) : "r"(addr));
}
__device__ __forceinline__ void mma_bf16(float* d, const uint32_t* a,
                                         uint32_t b0, uint32_t b1) {
    asm volatile(
        "mma.sync.aligned.m16n8k16.row.col.f32.bf16.bf16.f32 "
        "{%0,%1,%2,%3},{%4,%5,%6,%7},{%8,%9},{%0,%1,%2,%3};"
        : "+f"(d[0]), "+f"(d[1]), "+f"(d[2]), "+f"(d[3])
        : "r"(a[0]), "r"(a[1]), "r"(a[2]), "r"(a[3]), "r"(b0), "r"(b1));
}

// ======================= mma.sync bf16-split GEMM (unchanged) ==============
#define TGSTG  65536
#define TG_SMEM (2 * TGSTG)

__device__ __forceinline__ void tg_load(
    const __nv_bfloat16* ah, const __nv_bfloat16* al,
    const __nv_bfloat16* bh, const __nv_bfloat16* bl,
    long m0, long n0, int lda, int aoff, int ldb, int kc, char* buf, int tid)
{
#pragma unroll
    for (int t4 = 0; t4 < 4; t4++) {
        const __nv_bfloat16* base = t4 == 0 ? ah : t4 == 1 ? al : t4 == 2 ? bh : bl;
        long r0 = (t4 < 2) ? m0 : n0;
        long ld = (t4 < 2) ? lda : ldb;
        int  o0 = ((t4 < 2) ? aoff : 0) + kc;
#pragma unroll
        for (int i = 0; i < 4; i++) {
            int v = tid + i * 256;
            int row = v >> 3, c16 = v & 7;
            uint32_t byte = row * 128 + c16 * 16;
            uint32_t sw = byte ^ ((byte >> 3) & 0x70);
            cp16(buf + t4 * 16384 + sw, base + (r0 + row) * ld + o0 + c16 * 8);
        }
    }
}

__global__ __launch_bounds__(256, 1)
void tgemm(const __nv_bfloat16* __restrict__ ah, const __nv_bfloat16* __restrict__ al,
           int lda, int aoff,
           const __nv_bfloat16* __restrict__ bth, const __nv_bfloat16* __restrict__ btl,
           const float* __restrict__ bias, float* __restrict__ C, int ldc, int K)
{
    extern __shared__ char smb[];
    const int tid = threadIdx.x, wid = tid >> 5, lane = tid & 31;
    const long m0 = blockIdx.y * 128L, n0 = blockIdx.x * 128L;
    const int wm = wid & 1;
    const int wn = wid >> 1;

    float acc[16][4];
#pragma unroll
    for (int i = 0; i < 16; i++)
#pragma unroll
        for (int j = 0; j < 4; j++) acc[i][j] = 0.0f;

    const int nch = K >> 6;
    tg_load(ah, al, bth, btl, m0, n0, lda, aoff, K, 0, smb, tid);
    asm volatile("cp.async.commit_group;\n" ::: "memory");

    const int a_lrow = lane & 15;
    const int a_koff = (lane >> 4) * 16;
    const int b_lrow = (lane & 7) + ((lane >> 4) << 3);
    const int b_koff = ((lane >> 3) & 1) << 4;

    for (int c = 0; c < nch; c++) {
        if (c + 1 < nch) {
            tg_load(ah, al, bth, btl, m0, n0, lda, aoff, K, (c + 1) * 64,
                    smb + ((c + 1) & 1) * TGSTG, tid);
            asm volatile("cp.async.commit_group;\n" ::: "memory");
            asm volatile("cp.async.wait_group 1;\n" ::: "memory");
        } else {
            asm volatile("cp.async.wait_group 0;\n" ::: "memory");
        }
        __syncthreads();

        const uint32_t sb = s2u(smb + (c & 1) * TGSTG);

#pragma unroll
        for (int ks = 0; ks < 4; ks++) {
            uint32_t afh[4][4], afl[4][4], bfh[2][4], bfl[2][4];
            const int akb = ks * 32 + a_koff;
#pragma unroll
            for (int im = 0; im < 4; im++) {
                int row = wm * 64 + im * 16 + a_lrow;
                uint32_t off = row * 128 + (akb ^ ((row & 7) << 4));
                ldsm_x4(afh[im], sb + off);
                ldsm_x4(afl[im], sb + 16384 + off);
            }
            const int bkb = ks * 32 + b_koff;
#pragma unroll
            for (int inp = 0; inp < 2; inp++) {
                int row = wn * 32 + inp * 16 + b_lrow;
                uint32_t off = row * 128 + (bkb ^ ((row & 7) << 4));
                ldsm_x4(bfh[inp], sb + 32768 + off);
                ldsm_x4(bfl[inp], sb + 49152 + off);
            }
#pragma unroll
            for (int im = 0; im < 4; im++)
#pragma unroll
                for (int in_ = 0; in_ < 4; in_++) {
                    uint32_t h0 = bfh[in_ >> 1][(in_ & 1) * 2];
                    uint32_t h1 = bfh[in_ >> 1][(in_ & 1) * 2 + 1];
                    uint32_t l0 = bfl[in_ >> 1][(in_ & 1) * 2];
                    uint32_t l1 = bfl[in_ >> 1][(in_ & 1) * 2 + 1];
                    float* d = acc[im * 4 + in_];
                    mma_bf16(d, afh[im], h0, h1);
                    mma_bf16(d, afh[im], l0, l1);
                    mma_bf16(d, afl[im], h0, h1);
                }
        }
        __syncthreads();
    }

    const long mb = m0 + wm * 64 + (lane >> 2);
    const int  nb = (int)n0 + wn * 32 + (lane & 3) * 2;
#pragma unroll
    for (int im = 0; im < 4; im++) {
#pragma unroll
        for (int in_ = 0; in_ < 4; in_++) {
            const float* d = acc[im * 4 + in_];
            int col = nb + in_ * 8;
            float2 bv = *(const float2*)&bias[col];
            long r1 = mb + im * 16;
            *(float2*)&C[r1 * (long)ldc + col] =
                make_float2(d[0] + bv.x, d[1] + bv.y);
            *(float2*)&C[(r1 + 8) * (long)ldc + col] =
                make_float2(d[2] + bv.x, d[3] + bv.y);
        }
    }
}

// ======================= conversion kernels ================================
__global__ void split_f32(const float* __restrict__ s, __nv_bfloat16* __restrict__ h,
                          __nv_bfloat16* __restrict__ l, int n)
{
    int i = blockIdx.x * 256 + threadIdx.x;
    if (i >= n) return;
    float v = s[i];
    __nv_bfloat16 hv = __float2bfloat16(v);
    h[i] = hv;
    l[i] = __float2bfloat16(v - __bfloat162float(hv));
}

__global__ void tsplit(const float* __restrict__ w, __nv_bfloat16* __restrict__ th,
                       __nv_bfloat16* __restrict__ tl, int K, int N)
{
    __shared__ float t[32][33];
    int nb = blockIdx.x * 32, kb = blockIdx.y * 32;
    for (int r = threadIdx.y; r < 32; r += 8) {
        int n = nb + threadIdx.x;
        t[r][threadIdx.x] = (n < N) ? w[(long)(kb + r) * N + n] : 0.0f;
    }
    __syncthreads();
    for (int r = threadIdx.y; r < 32; r += 8) {
        long n = nb + r, k = kb + threadIdx.x;
        float v = t[threadIdx.x][r];
        __nv_bfloat16 hv = __float2bfloat16(v);
        th[n * K + k] = hv;
        tl[n * K + k] = __float2bfloat16(v - __bfloat162float(hv));
    }
}

__global__ void pad64(const float* __restrict__ b, float* __restrict__ o)
{
    int i = threadIdx.x;
    o[i] = (i < 64) ? b[i] : 0.0f;
}

// gather q/k main+pos into [row][h][192] bf16 hi/lo
__global__ void catsplit(const float* __restrict__ mainp, const float* __restrict__ posp,
                         int posld, int poshs,
                         __nv_bfloat16* __restrict__ oh, __nv_bfloat16* __restrict__ ol)
{
    long idx = blockIdx.x * 256L + threadIdx.x;
    long row = idx / 3072;
    int rem = (int)(idx - row * 3072);
    int h = rem / 192, d = rem - h * 192;
    float v = (d < 128) ? mainp[row * 2048 + h * 128 + d]
                        : posp[row * (long)posld + h * poshs + (d - 128)];
    __nv_bfloat16 hv = __float2bfloat16(v);
    oh[idx] = hv;
    ol[idx] = __float2bfloat16(v - __bfloat162float(hv));
}

// ======================= fused RoPE ========================================
#define LOG2_THETA_OVER_32 0.48780126482613787f
#define QROT (MROWS * 512)
#define KROT (MROWS * 32)

__global__ void rope_kernel(float* __restrict__ pq, float* __restrict__ pk)
{
    int idx = blockIdx.x * 256 + threadIdx.x;
    if (idx >= QROT + KROT) return;
    float* base; int s, i;
    if (idx < QROT) {
        int r = idx >> 9, rem = idx & 511, h = rem >> 5;
        i = rem & 31; s = r & (SS - 1);
        base = pq + (long)r * 1024 + h * PHD + i;
    } else {
        int k = idx - QROT, r = k >> 5;
        i = k & 31; s = r & (SS - 1);
        base = pk + (long)r * 128 + i;
    }
    float ang = (float)s * exp2f(-(float)i * LOG2_THETA_OVER_32);
    float sn, cs; sincosf(ang, &sn, &cs);
    float x0 = base[0], x1 = base[32];
    base[0]  = x0 * cs - x1 * sn;
    base[32] = x1 * cs + x0 * sn;
}

// ======================= tensor-core flash attention =======================
// 128 q-rows x 64 kv tile. 8 warps, warp w owns q-rows [16w,16w+16).
// Q/K 3-term split mma for scores; fp32 softmax on fragments; P split
// bf16 hi/lo in smem; P@V 3-term mma with V^T tiles.
#define AQH 0
#define AQL 49152
#define AKH 98304
#define AKL 122880
#define AVH 147456
#define AVL 163840
#define APH 180224
#define APL 196608
#define ATTN_SMEM 212992

__device__ __forceinline__ uint32_t sw384(int row, int seg) {
    return row * 384 + (((seg & 24) | ((seg ^ row) & 7)) << 4);
}
__device__ __forceinline__ uint32_t sw128s(int row, int seg) {
    return row * 128 + (((seg ^ row) & 7) << 4);
}

__global__ __launch_bounds__(256, 1)
void attn_mma(const __nv_bfloat16* __restrict__ qch, const __nv_bfloat16* __restrict__ qcl,
              const __nv_bfloat16* __restrict__ kch, const __nv_bfloat16* __restrict__ kcl,
              const __nv_bfloat16* __restrict__ vth, const __nv_bfloat16* __restrict__ vtl,
              float* __restrict__ outp)
{
    extern __shared__ char smb[];
    const uint32_t sb = s2u(smb);
    const int tid = threadIdx.x, lane = tid & 31, w = tid >> 5;
    const int bh = blockIdx.y, b = bh >> 4, h = bh & 15;
    const int qti = (int)gridDim.x - 1 - (int)blockIdx.x;
    const int m0 = qti * 128, nk = 2 * qti + 2;
    const long rowbase = (long)b * SS;
    const float scale = 0.07216878364870323f;   // 1/sqrt(192)

    // ---- prefetch Q (whole tile) + K/V tile 0 ----
#pragma unroll
    for (int i = 0; i < 12; i++) {
        int v = tid + i * 256;                 // 0..3071
        int row = v / 24, seg = v - row * 24;
        long g = ((rowbase + m0 + row) * 16 + h) * 192 + seg * 8;
        cp16(smb + AQH + sw384(row, seg), qch + g);
        cp16(smb + AQL + sw384(row, seg), qcl + g);
    }
#pragma unroll
    for (int i = 0; i < 6; i++) {
        int v = tid + i * 256;                 // 0..1535
        int row = v / 24, seg = v - row * 24;
        long g = ((rowbase + row) * 16 + h) * 192 + seg * 8;
        cp16(smb + AKH + sw384(row, seg), kch + g);
        cp16(smb + AKL + sw384(row, seg), kcl + g);
    }
#pragma unroll
    for (int i = 0; i < 4; i++) {
        int v = tid + i * 256;                 // 0..1023
        int row = v >> 3, seg = v & 7;
        long g = (long)(h * 128 + row) * MROWS + rowbase + seg * 8;
        cp16(smb + AVH + sw128s(row, seg), vth + g);
        cp16(smb + AVL + sw128s(row, seg), vtl + g);
    }
    asm volatile("cp.async.commit_group;\n" ::: "memory");

    float oc[16][4];
#pragma unroll
    for (int i = 0; i < 16; i++)
#pragma unroll
        for (int j = 0; j < 4; j++) oc[i][j] = 0.0f;
    float mi[2] = {-1e30f, -1e30f}, li[2] = {0.0f, 0.0f};

    const int a_lrow = lane & 15;
    const int a_ksel = lane >> 4;
    const int b_lrow = (lane & 7) + ((lane >> 4) << 3);
    const int b_ksel = (lane >> 3) & 1;

    for (int t = 0; t < nk; ++t) {
        asm volatile("cp.async.wait_group 0;\n" ::: "memory");
        __syncthreads();                       // K(t), V(t) visible
        const int n0 = t * 64;

        // ---- scores: warp-tile 16x64 over d=192 ----
        float sc[8][4];
#pragma unroll
        for (int i = 0; i < 8; i++)
#pragma unroll
            for (int j = 0; j < 4; j++) sc[i][j] = 0.0f;

#pragma unroll
        for (int ks = 0; ks < 12; ks++) {
            uint32_t afh[4], afl[4];
            {
                int row = w * 16 + a_lrow;
                int seg = ks * 2 + a_ksel;
                ldsm_x4(afh, sb + AQH + sw384(row, seg));
                ldsm_x4(afl, sb + AQL + sw384(row, seg));
            }
#pragma unroll
            for (int blk = 0; blk < 4; blk++) {
                uint32_t bh_[4], bl_[4];
                int row = blk * 16 + b_lrow;
                int seg = ks * 2 + b_ksel;
                ldsm_x4(bh_, sb + AKH + sw384(row, seg));
                ldsm_x4(bl_, sb + AKL + sw384(row, seg));
#pragma unroll
                for (int hf = 0; hf < 2; hf++) {
                    float* d = sc[blk * 2 + hf];
                    mma_bf16(d, afh, bh_[hf * 2], bh_[hf * 2 + 1]);
                    mma_bf16(d, afh, bl_[hf * 2], bl_[hf * 2 + 1]);
                    mma_bf16(d, afl, bh_[hf * 2], bh_[hf * 2 + 1]);
                }
            }
        }

        // ---- softmax on fragments (rows lane>>2 and +8) ----
        const bool diag = (t >= 2 * qti);
        const int rbase = m0 + w * 16 + (lane >> 2);
        const int cbase = n0 + (lane & 3) * 2;
#pragma unroll
        for (int a = 0; a < 2; a++) {
            float m_t = -1e30f;
#pragma unroll
            for (int nb = 0; nb < 8; nb++)
#pragma unroll
                for (int c = 0; c < 2; c++) {
                    float s = sc[nb][2 * a + c] * scale;
                    if (diag && (cbase + nb * 8 + c) > (rbase + 8 * a)) s = -1e30f;
                    sc[nb][2 * a + c] = s;
                    m_t = fmaxf(m_t, s);
                }
            m_t = fmaxf(m_t, __shfl_xor_sync(0xffffffffu, m_t, 1));
            m_t = fmaxf(m_t, __shfl_xor_sync(0xffffffffu, m_t, 2));
            float mnew = fmaxf(mi[a], m_t);
            float alpha = __expf(mi[a] - mnew);
            float rsum = 0.0f;
#pragma unroll
            for (int nb = 0; nb < 8; nb++)
#pragma unroll
                for (int c = 0; c < 2; c++) {
                    float p = __expf(sc[nb][2 * a + c] - mnew);
                    sc[nb][2 * a + c] = p;
                    rsum += p;
                }
            rsum += __shfl_xor_sync(0xffffffffu, rsum, 1);
            rsum += __shfl_xor_sync(0xffffffffu, rsum, 2);
            li[a] = li[a] * alpha + rsum;
            mi[a] = mnew;
#pragma unroll
            for (int nb2 = 0; nb2 < 16; nb2++) {
                oc[nb2][2 * a]     *= alpha;
                oc[nb2][2 * a + 1] *= alpha;
            }
        }

        // ---- store P hi/lo to smem (own warp's rows only) ----
#pragma unroll
        for (int a = 0; a < 2; a++) {
            int row = w * 16 + (lane >> 2) + 8 * a;
#pragma unroll
            for (int nb = 0; nb < 8; nb++) {
                float p0 = sc[nb][2 * a], p1 = sc[nb][2 * a + 1];
                __nv_bfloat162 hi2 = __floats2bfloat162_rn(p0, p1);
                float2 hf = __bfloat1622float2(hi2);
                __nv_bfloat162 lo2 = __floats2bfloat162_rn(p0 - hf.x, p1 - hf.y);
                uint32_t off = sw128s(row, nb) + (lane & 3) * 4;
                *(uint32_t*)(smb + APH + off) = *(uint32_t*)&hi2;
                *(uint32_t*)(smb + APL + off) = *(uint32_t*)&lo2;
            }
        }
        __syncwarp();
        __syncthreads();                        // all K reads done

        if (t + 1 < nk) {                       // prefetch K(t+1) over P@V
#pragma unroll
            for (int i = 0; i < 6; i++) {
                int v = tid + i * 256;
                int row = v / 24, seg = v - row * 24;
                long g = ((rowbase + n0 + 64 + row) * 16 + h) * 192 + seg * 8;
                cp16(smb + AKH + sw384(row, seg), kch + g);
                cp16(smb + AKL + sw384(row, seg), kcl + g);
            }
            asm volatile("cp.async.commit_group;\n" ::: "memory");
        }

        // ---- P @ V^T : warp-tile 16 x 128 over k=64 ----
#pragma unroll
        for (int ks = 0; ks < 4; ks++) {
            uint32_t aph[4], apl[4];
            {
                int row = w * 16 + a_lrow;
                int seg = ks * 2 + a_ksel;
                ldsm_x4(aph, sb + APH + sw128s(row, seg));
                ldsm_x4(apl, sb + APL + sw128s(row, seg));
            }
#pragma unroll
            for (int blk = 0; blk < 8; blk++) {
                uint32_t bh_[4], bl_[4];
                int row = blk * 16 + b_lrow;
                int seg = ks * 2 + b_ksel;
                ldsm_x4(bh_, sb + AVH + sw128s(row, seg));
                ldsm_x4(bl_, sb + AVL + sw128s(row, seg));
#pragma unroll
                for (int hf = 0; hf < 2; hf++) {
                    float* d = oc[blk * 2 + hf];
                    mma_bf16(d, aph, bh_[hf * 2], bh_[hf * 2 + 1]);
                    mma_bf16(d, aph, bl_[hf * 2], bl_[hf * 2 + 1]);
                    mma_bf16(d, apl, bh_[hf * 2], bh_[hf * 2 + 1]);
                }
            }
        }
        __syncthreads();                        // all V reads done

        if (t + 1 < nk) {                       // prefetch V(t+1) over next scores
#pragma unroll
            for (int i = 0; i < 4; i++) {
                int v = tid + i * 256;
                int row = v >> 3, seg = v & 7;
                long g = (long)(h * 128 + row) * MROWS + rowbase + n0 + 64 + seg * 8;
                cp16(smb + AVH + sw128s(row, seg), vth + g);
                cp16(smb + AVL + sw128s(row, seg), vtl + g);
            }
            asm volatile("cp.async.commit_group;\n" ::: "memory");
        }
    }

    // ---- epilogue: normalize + store [b,s,h,d] ----
#pragma unroll
    for (int nb2 = 0; nb2 < 16; nb2++) {
        int dcol = nb2 * 8 + (lane & 3) * 2;
#pragma unroll
        for (int a = 0; a < 2; a++) {
            long row = rowbase + m0 + w * 16 + (lane >> 2) + 8 * a;
            float inv = 1.0f / li[a];
            *(float2*)&outp[row * DMODEL + h * HD + dcol] =
                make_float2(oc[nb2][2 * a] * inv, oc[nb2][2 * a + 1] * inv);
        }
    }
}

// ======================= launch ============================================
#define SYM(p, s) cudaGetSymbolAddress((void**)&p, s)

extern "C" void kernel_launch(void* const* d_in, const int* in_sizes, int n_in,
                              void* d_out, int out_size)
{
    const float* x      = (const float*)d_in[0];
    const float* w_qkv  = (const float*)d_in[1];
    const float* b_qkv  = (const float*)d_in[2];
    const float* w_qup  = (const float*)d_in[3];
    const float* b_qup  = (const float*)d_in[4];
    const float* w_kup  = (const float*)d_in[5];
    const float* b_kup  = (const float*)d_in[6];
    const float* w_vup  = (const float*)d_in[7];
    const float* b_vup  = (const float*)d_in[8];
    const float* w_qpos = (const float*)d_in[9];
    const float* b_qpos = (const float*)d_in[10];
    const float* w_kpos = (const float*)d_in[11];
    const float* b_kpos = (const float*)d_in[12];
    const float* w_o    = (const float*)d_in[13];
    const float* b_o    = (const float*)d_in[14];
    float* out = (float*)d_out;

    float *latent, *qmain, *kmain, *vmain, *posq, *posk, *attnb, *bk128;
    SYM(latent, g_latent); SYM(qmain, g_qmain); SYM(kmain, g_kmain);
    SYM(vmain, g_vmain);   SYM(posq, g_posq);   SYM(posk, g_posk);
    SYM(attnb, g_attn);    SYM(bk128, g_bk128);
    __nv_bfloat16 *xh,*xl,*lh,*ll,*abh,*abl,*wqkvh,*wqkvl,*wkph,*wkpl,
                  *wquh,*wqul,*wkuh,*wkul,*wvuh,*wvul,*wqph,*wqpl,*woh,*wol,
                  *qch,*qcl,*kch,*kcl,*vth,*vtl;
    SYM(xh,g_xh); SYM(xl,g_xl); SYM(lh,g_lh); SYM(ll,g_ll);
    SYM(abh,g_abh); SYM(abl,g_abl);
    SYM(wqkvh,g_wqkvh); SYM(wqkvl,g_wqkvl); SYM(wkph,g_wkph); SYM(wkpl,g_wkpl);
    SYM(wquh,g_wquh); SYM(wqul,g_wqul); SYM(wkuh,g_wkuh); SYM(wkul,g_wkul);
    SYM(wvuh,g_wvuh); SYM(wvul,g_wvul); SYM(wqph,g_wqph); SYM(wqpl,g_wqpl);
    SYM(woh,g_woh); SYM(wol,g_wol);
    SYM(qch,g_qch); SYM(qcl,g_qcl); SYM(kch,g_kch); SYM(kcl,g_kcl);
    SYM(vth,g_vth); SYM(vtl,g_vtl);

    cudaFuncSetAttribute(tgemm, cudaFuncAttributeMaxDynamicSharedMemorySize, TG_SMEM);
    cudaFuncSetAttribute(attn_mma, cudaFuncAttributeMaxDynamicSharedMemorySize,
                         ATTN_SMEM);
    dim3 t8(32, 8);

    pad64<<<1, 128>>>(b_kpos, bk128);
    split_f32<<<(MROWS * DMODEL) / 256, 256>>>(x, xh, xl, MROWS * DMODEL);
    tsplit<<<dim3(1536 / 32, 2048 / 32), t8>>>(w_qkv, wqkvh, wqkvl, 2048, 1536);
    // latent = x @ w_qkv
    tgemm<<<dim3(12, 32), 256, TG_SMEM>>>(xh, xl, DMODEL, 0, wqkvh, wqkvl,
                                          b_qkv, latent, 1536, DMODEL);
    tsplit<<<dim3(128 / 32, 2048 / 32), t8>>>(w_kpos, wkph, wkpl, 2048, PHD);
    // posk = x @ w_kpos (N padded to 128)
    tgemm<<<dim3(1, 32), 256, TG_SMEM>>>(xh, xl, DMODEL, 0, wkph, wkpl,
                                         bk128, posk, 128, DMODEL);
    split_f32<<<(MROWS * 1536) / 256, 256>>>(latent, lh, ll, MROWS * 1536);
    tsplit<<<dim3(2048 / 32, 512 / 32), t8>>>(w_qup, wquh, wqul, 512, 2048);
    tsplit<<<dim3(2048 / 32, 512 / 32), t8>>>(w_kup, wkuh, wkul, 512, 2048);
    tsplit<<<dim3(2048 / 32, 512 / 32), t8>>>(w_vup, wvuh, wvul, 512, 2048);
    tsplit<<<dim3(1024 / 32, 512 / 32), t8>>>(w_qpos, wqph, wqpl, 512, 1024);
    tgemm<<<dim3(16, 32), 256, TG_SMEM>>>(lh, ll, 1536, 0,    wquh, wqul, b_qup,  qmain, DMODEL, LAT);
    tgemm<<<dim3(16, 32), 256, TG_SMEM>>>(lh, ll, 1536, 512,  wkuh, wkul, b_kup,  kmain, DMODEL, LAT);
    tgemm<<<dim3(16, 32), 256, TG_SMEM>>>(lh, ll, 1536, 1024, wvuh, wvul, b_vup,  vmain, DMODEL, LAT);
    tgemm<<<dim3(8, 32), 256, TG_SMEM>>>(lh, ll, 1536, 0,     wqph, wqpl, b_qpos, posq,  1024,   LAT);
    rope_kernel<<<(QROT + KROT + 255) / 256, 256>>>(posq, posk);
    // attention operand prep
    catsplit<<<(MROWS * 16 * 192) / 256, 256>>>(qmain, posq, 1024, 64, qch, qcl);
    catsplit<<<(MROWS * 16 * 192) / 256, 256>>>(kmain, posk, 128, 0, kch, kcl);
    tsplit<<<dim3(2048 / 32, MROWS / 32), t8>>>(vmain, vth, vtl, MROWS, DMODEL);
    // attention
    attn_mma<<<dim3(SS / 128, BB * NHD), 256, ATTN_SMEM>>>(
        qch, qcl, kch, kcl, vth, vtl, attnb);
    // output projection
    split_f32<<<(MROWS * DMODEL) / 256, 256>>>(attnb, abh, abl, MROWS * DMODEL);
    tsplit<<<dim3(2048 / 32, 2048 / 32), t8>>>(w_o, woh, wol, 2048, 2048);
    tgemm<<<dim3(16, 32), 256, TG_SMEM>>>(abh, abl, DMODEL, 0, woh, wol,
                                          b_o, out, DMODEL, DMODEL);
}

// round 13
// speedup vs baseline: 2.5869x; 1.0541x over previous
#include <cuda_runtime.h>
#include <cuda_bf16.h>
#include <math.h>
#include <stdint.h>

#define BB     2
#define SS     2048
#define DMODEL 2048
#define LAT    512
#define NHD    16
#define HD     128
#define PHD    64
#define DQK    192
#define MROWS  4096

// ---------------- fp32 scratch ----------------
__device__ float g_vmain [MROWS * DMODEL];
__device__ float g_posq  [MROWS * 1024];
__device__ float g_posk  [MROWS * 128];
__device__ float g_bk128 [128];

// ---------------- bf16 split operands ----------------
__device__ __nv_bfloat16 g_xh[MROWS*DMODEL], g_xl[MROWS*DMODEL];
__device__ __nv_bfloat16 g_lh[MROWS*1536],   g_ll[MROWS*1536];
__device__ __nv_bfloat16 g_abh[MROWS*DMODEL],g_abl[MROWS*DMODEL];
__device__ __nv_bfloat16 g_wqkvh[1536*2048], g_wqkvl[1536*2048];
__device__ __nv_bfloat16 g_wkph[128*2048],   g_wkpl[128*2048];
__device__ __nv_bfloat16 g_wquh[2048*512],   g_wqul[2048*512];
__device__ __nv_bfloat16 g_wkuh[2048*512],   g_wkul[2048*512];
__device__ __nv_bfloat16 g_wvuh[2048*512],   g_wvul[2048*512];
__device__ __nv_bfloat16 g_wqph[1024*512],   g_wqpl[1024*512];
__device__ __nv_bfloat16 g_woh[2048*2048],   g_wol[2048*2048];
// attention operands
__device__ __nv_bfloat16 g_qch[MROWS*16*192], g_qcl[MROWS*16*192];
__device__ __nv_bfloat16 g_kch[MROWS*16*192], g_kcl[MROWS*16*192];
__device__ __nv_bfloat16 g_vth[2048*MROWS],   g_vtl[2048*MROWS];

// ======================= helpers ===========================================
__device__ __forceinline__ uint32_t s2u(const void* p) {
    return (uint32_t)__cvta_generic_to_shared(const_cast<void*>(p));
}
__device__ __forceinline__ void cp16(void* d, const void* s) {
    asm volatile("cp.async.cg.shared.global [%0],[%1],16;\n"
                 :: "r"(s2u(d)), "l"(s) : "memory");
}
__device__ __forceinline__ void ldsm_x4(uint32_t* r, uint32_t addr) {
    asm volatile("ldmatrix.sync.aligned.m8n8.x4.shared.b16 {%0,%1,%2,%3},[%4];"
                 : "=r"(r[0]), "=r"(r[1]), "=r"(r[2]), "=r"(r[3]) : "r"(addr));
}
__device__ __forceinline__ void mma_bf16(float* d, const uint32_t* a,
                                         uint32_t b0, uint32_t b1) {
    asm volatile(
        "mma.sync.aligned.m16n8k16.row.col.f32.bf16.bf16.f32 "
        "{%0,%1,%2,%3},{%4,%5,%6,%7},{%8,%9},{%0,%1,%2,%3};"
        : "+f"(d[0]), "+f"(d[1]), "+f"(d[2]), "+f"(d[3])
        : "r"(a[0]), "r"(a[1]), "r"(a[2]), "r"(a[3]), "r"(b0), "r"(b1));
}
// pack two fp32 into bf16 hi pair + lo pair
__device__ __forceinline__ void split2(float v0, float v1, uint32_t& hi, uint32_t& lo) {
    __nv_bfloat162 h2 = __floats2bfloat162_rn(v0, v1);
    float2 hf = __bfloat1622float2(h2);
    __nv_bfloat162 l2 = __floats2bfloat162_rn(v0 - hf.x, v1 - hf.y);
    hi = *(uint32_t*)&h2;
    lo = *(uint32_t*)&l2;
}

// ======================= mma.sync bf16-split GEMM ==========================
// C = A*W^T + bias. Outputs: optional fp32 Cf[ldc], optional bf16 split
// Ch/Cl (remap=0: linear ldc; remap=1: n -> row*3072 + (n>>7)*192 + (n&127)).
#define TGSTG  65536
#define TG_SMEM (2 * TGSTG)

__device__ __forceinline__ void tg_load(
    const __nv_bfloat16* ah, const __nv_bfloat16* al,
    const __nv_bfloat16* bh, const __nv_bfloat16* bl,
    long m0, long n0, int lda, int aoff, int ldb, int kc, char* buf, int tid)
{
#pragma unroll
    for (int t4 = 0; t4 < 4; t4++) {
        const __nv_bfloat16* base = t4 == 0 ? ah : t4 == 1 ? al : t4 == 2 ? bh : bl;
        long r0 = (t4 < 2) ? m0 : n0;
        long ld = (t4 < 2) ? lda : ldb;
        int  o0 = ((t4 < 2) ? aoff : 0) + kc;
#pragma unroll
        for (int i = 0; i < 4; i++) {
            int v = tid + i * 256;
            int row = v >> 3, c16 = v & 7;
            uint32_t byte = row * 128 + c16 * 16;
            uint32_t sw = byte ^ ((byte >> 3) & 0x70);
            cp16(buf + t4 * 16384 + sw, base + (r0 + row) * ld + o0 + c16 * 8);
        }
    }
}

__global__ __launch_bounds__(256, 1)
void tgemm(const __nv_bfloat16* __restrict__ ah, const __nv_bfloat16* __restrict__ al,
           int lda, int aoff,
           const __nv_bfloat16* __restrict__ bth, const __nv_bfloat16* __restrict__ btl,
           const float* __restrict__ bias,
           float* __restrict__ Cf,
           __nv_bfloat16* __restrict__ Ch, __nv_bfloat16* __restrict__ Cl,
           int ldc, int K, int remap)
{
    extern __shared__ char smb[];
    const int tid = threadIdx.x, wid = tid >> 5, lane = tid & 31;
    const long m0 = blockIdx.y * 128L, n0 = blockIdx.x * 128L;
    const int wm = wid & 1;
    const int wn = wid >> 1;

    float acc[16][4];
#pragma unroll
    for (int i = 0; i < 16; i++)
#pragma unroll
        for (int j = 0; j < 4; j++) acc[i][j] = 0.0f;

    const int nch = K >> 6;
    tg_load(ah, al, bth, btl, m0, n0, lda, aoff, K, 0, smb, tid);
    asm volatile("cp.async.commit_group;\n" ::: "memory");

    const int a_lrow = lane & 15;
    const int a_koff = (lane >> 4) * 16;
    const int b_lrow = (lane & 7) + ((lane >> 4) << 3);
    const int b_koff = ((lane >> 3) & 1) << 4;

    for (int c = 0; c < nch; c++) {
        if (c + 1 < nch) {
            tg_load(ah, al, bth, btl, m0, n0, lda, aoff, K, (c + 1) * 64,
                    smb + ((c + 1) & 1) * TGSTG, tid);
            asm volatile("cp.async.commit_group;\n" ::: "memory");
            asm volatile("cp.async.wait_group 1;\n" ::: "memory");
        } else {
            asm volatile("cp.async.wait_group 0;\n" ::: "memory");
        }
        __syncthreads();

        const uint32_t sb = s2u(smb + (c & 1) * TGSTG);

#pragma unroll
        for (int ks = 0; ks < 4; ks++) {
            uint32_t afh[4][4], afl[4][4], bfh[2][4], bfl[2][4];
            const int akb = ks * 32 + a_koff;
#pragma unroll
            for (int im = 0; im < 4; im++) {
                int row = wm * 64 + im * 16 + a_lrow;
                uint32_t off = row * 128 + (akb ^ ((row & 7) << 4));
                ldsm_x4(afh[im], sb + off);
                ldsm_x4(afl[im], sb + 16384 + off);
            }
            const int bkb = ks * 32 + b_koff;
#pragma unroll
            for (int inp = 0; inp < 2; inp++) {
                int row = wn * 32 + inp * 16 + b_lrow;
                uint32_t off = row * 128 + (bkb ^ ((row & 7) << 4));
                ldsm_x4(bfh[inp], sb + 32768 + off);
                ldsm_x4(bfl[inp], sb + 49152 + off);
            }
#pragma unroll
            for (int im = 0; im < 4; im++)
#pragma unroll
                for (int in_ = 0; in_ < 4; in_++) {
                    uint32_t h0 = bfh[in_ >> 1][(in_ & 1) * 2];
                    uint32_t h1 = bfh[in_ >> 1][(in_ & 1) * 2 + 1];
                    uint32_t l0 = bfl[in_ >> 1][(in_ & 1) * 2];
                    uint32_t l1 = bfl[in_ >> 1][(in_ & 1) * 2 + 1];
                    float* d = acc[im * 4 + in_];
                    mma_bf16(d, afh[im], h0, h1);
                    mma_bf16(d, afh[im], l0, l1);
                    mma_bf16(d, afl[im], h0, h1);
                }
        }
        __syncthreads();
    }

    // ---- epilogue: bias + (fp32 and/or bf16-split, optional remap) ----
    const long mb = m0 + wm * 64 + (lane >> 2);
    const int  nb = (int)n0 + wn * 32 + (lane & 3) * 2;
#pragma unroll
    for (int im = 0; im < 4; im++) {
#pragma unroll
        for (int in_ = 0; in_ < 4; in_++) {
            const float* d = acc[im * 4 + in_];
            int col = nb + in_ * 8;
            float2 bv = *(const float2*)&bias[col];
            float v00 = d[0] + bv.x, v01 = d[1] + bv.y;   // row r1
            float v10 = d[2] + bv.x, v11 = d[3] + bv.y;   // row r1+8
            long r1 = mb + im * 16, r2 = r1 + 8;
            if (Cf) {
                *(float2*)&Cf[r1 * (long)ldc + col] = make_float2(v00, v01);
                *(float2*)&Cf[r2 * (long)ldc + col] = make_float2(v10, v11);
            }
            if (Ch) {
                long i1, i2;
                if (remap) {
                    long o = (long)(col >> 7) * 192 + (col & 127);
                    i1 = r1 * 3072 + o;
                    i2 = r2 * 3072 + o;
                } else {
                    i1 = r1 * (long)ldc + col;
                    i2 = r2 * (long)ldc + col;
                }
                uint32_t hi, lo;
                split2(v00, v01, hi, lo);
                *(uint32_t*)&Ch[i1] = hi;  *(uint32_t*)&Cl[i1] = lo;
                split2(v10, v11, hi, lo);
                *(uint32_t*)&Ch[i2] = hi;  *(uint32_t*)&Cl[i2] = lo;
            }
        }
    }
}

// ======================= conversion kernels ================================
__global__ void split_f32(const float* __restrict__ s, __nv_bfloat16* __restrict__ h,
                          __nv_bfloat16* __restrict__ l, int n)
{
    int i = blockIdx.x * 256 + threadIdx.x;
    if (i >= n) return;
    float v = s[i];
    __nv_bfloat16 hv = __float2bfloat16(v);
    h[i] = hv;
    l[i] = __float2bfloat16(v - __bfloat162float(hv));
}

__global__ void tsplit(const float* __restrict__ w, __nv_bfloat16* __restrict__ th,
                       __nv_bfloat16* __restrict__ tl, int K, int N)
{
    __shared__ float t[32][33];
    int nb = blockIdx.x * 32, kb = blockIdx.y * 32;
    for (int r = threadIdx.y; r < 32; r += 8) {
        int n = nb + threadIdx.x;
        t[r][threadIdx.x] = (n < N) ? w[(long)(kb + r) * N + n] : 0.0f;
    }
    __syncthreads();
    for (int r = threadIdx.y; r < 32; r += 8) {
        long n = nb + r, k = kb + threadIdx.x;
        float v = t[threadIdx.x][r];
        __nv_bfloat16 hv = __float2bfloat16(v);
        th[n * K + k] = hv;
        tl[n * K + k] = __float2bfloat16(v - __bfloat162float(hv));
    }
}

__global__ void pad64(const float* __restrict__ b, float* __restrict__ o)
{
    int i = threadIdx.x;
    o[i] = (i < 64) ? b[i] : 0.0f;
}

// ======================= fused RoPE -> bf16 split ==========================
#define LOG2_THETA_OVER_32 0.48780126482613787f
#define QROT (MROWS * 512)
#define KROT (MROWS * 32)

// rotate posq, write into qch/qcl pos-columns [row][h][128+i]
__global__ void rope_q_split(const float* __restrict__ pq,
                             __nv_bfloat16* __restrict__ qh, __nv_bfloat16* __restrict__ ql)
{
    int idx = blockIdx.x * 256 + threadIdx.x;
    if (idx >= QROT) return;
    int r = idx >> 9, rem = idx & 511, h = rem >> 5, i = rem & 31;
    int s = r & (SS - 1);
    float ang = (float)s * exp2f(-(float)i * LOG2_THETA_OVER_32);
    float sn, cs; sincosf(ang, &sn, &cs);
    float v0 = pq[(long)r * 1024 + h * 64 + i];
    float v1 = pq[(long)r * 1024 + h * 64 + i + 32];
    float y0 = v0 * cs - v1 * sn;
    float y1 = v1 * cs + v0 * sn;
    long base = (long)r * 3072 + h * 192 + 128 + i;
    __nv_bfloat16 h0 = __float2bfloat16(y0);
    __nv_bfloat16 h1 = __float2bfloat16(y1);
    qh[base]      = h0;  ql[base]      = __float2bfloat16(y0 - __bfloat162float(h0));
    qh[base + 32] = h1;  ql[base + 32] = __float2bfloat16(y1 - __bfloat162float(h1));
}

// rotate posk, broadcast into kch/kcl pos-columns for all 16 heads
__global__ void rope_k_split(const float* __restrict__ pk,
                             __nv_bfloat16* __restrict__ kh, __nv_bfloat16* __restrict__ kl)
{
    int idx = blockIdx.x * 256 + threadIdx.x;
    if (idx >= KROT) return;
    int r = idx >> 5, i = idx & 31;
    int s = r & (SS - 1);
    float ang = (float)s * exp2f(-(float)i * LOG2_THETA_OVER_32);
    float sn, cs; sincosf(ang, &sn, &cs);
    float v0 = pk[(long)r * 128 + i];
    float v1 = pk[(long)r * 128 + i + 32];
    float y0 = v0 * cs - v1 * sn;
    float y1 = v1 * cs + v0 * sn;
    __nv_bfloat16 h0 = __float2bfloat16(y0);
    __nv_bfloat16 h1 = __float2bfloat16(y1);
    __nv_bfloat16 l0 = __float2bfloat16(y0 - __bfloat162float(h0));
    __nv_bfloat16 l1 = __float2bfloat16(y1 - __bfloat162float(h1));
    long rb = (long)r * 3072 + 128 + i;
#pragma unroll
    for (int h = 0; h < 16; h++) {
        kh[rb + h * 192]      = h0;  kl[rb + h * 192]      = l0;
        kh[rb + h * 192 + 32] = h1;  kl[rb + h * 192 + 32] = l1;
    }
}

// ======================= tensor-core flash attention =======================
#define AQH 0
#define AQL 49152
#define AKH 98304
#define AKL 122880
#define AVH 147456
#define AVL 163840
#define APH 180224
#define APL 196608
#define ATTN_SMEM 212992

__device__ __forceinline__ uint32_t sw384(int row, int seg) {
    return row * 384 + (((seg & 24) | ((seg ^ row) & 7)) << 4);
}
__device__ __forceinline__ uint32_t sw128s(int row, int seg) {
    return row * 128 + (((seg ^ row) & 7) << 4);
}

__global__ __launch_bounds__(256, 1)
void attn_mma(const __nv_bfloat16* __restrict__ qch, const __nv_bfloat16* __restrict__ qcl,
              const __nv_bfloat16* __restrict__ kch, const __nv_bfloat16* __restrict__ kcl,
              const __nv_bfloat16* __restrict__ vth, const __nv_bfloat16* __restrict__ vtl,
              __nv_bfloat16* __restrict__ obh, __nv_bfloat16* __restrict__ obl)
{
    extern __shared__ char smb[];
    const uint32_t sb = s2u(smb);
    const int tid = threadIdx.x, lane = tid & 31, w = tid >> 5;
    const int bh = blockIdx.y, b = bh >> 4, h = bh & 15;
    const int qti = (int)gridDim.x - 1 - (int)blockIdx.x;
    const int m0 = qti * 128, nk = 2 * qti + 2;
    const long rowbase = (long)b * SS;
    const float scale = 0.07216878364870323f;

#pragma unroll
    for (int i = 0; i < 12; i++) {
        int v = tid + i * 256;
        int row = v / 24, seg = v - row * 24;
        long g = ((rowbase + m0 + row) * 16 + h) * 192 + seg * 8;
        cp16(smb + AQH + sw384(row, seg), qch + g);
        cp16(smb + AQL + sw384(row, seg), qcl + g);
    }
#pragma unroll
    for (int i = 0; i < 6; i++) {
        int v = tid + i * 256;
        int row = v / 24, seg = v - row * 24;
        long g = ((rowbase + row) * 16 + h) * 192 + seg * 8;
        cp16(smb + AKH + sw384(row, seg), kch + g);
        cp16(smb + AKL + sw384(row, seg), kcl + g);
    }
#pragma unroll
    for (int i = 0; i < 4; i++) {
        int v = tid + i * 256;
        int row = v >> 3, seg = v & 7;
        long g = (long)(h * 128 + row) * MROWS + rowbase + seg * 8;
        cp16(smb + AVH + sw128s(row, seg), vth + g);
        cp16(smb + AVL + sw128s(row, seg), vtl + g);
    }
    asm volatile("cp.async.commit_group;\n" ::: "memory");

    float oc[16][4];
#pragma unroll
    for (int i = 0; i < 16; i++)
#pragma unroll
        for (int j = 0; j < 4; j++) oc[i][j] = 0.0f;
    float mi[2] = {-1e30f, -1e30f}, li[2] = {0.0f, 0.0f};

    const int a_lrow = lane & 15;
    const int a_ksel = lane >> 4;
    const int b_lrow = (lane & 7) + ((lane >> 4) << 3);
    const int b_ksel = (lane >> 3) & 1;

    for (int t = 0; t < nk; ++t) {
        asm volatile("cp.async.wait_group 0;\n" ::: "memory");
        __syncthreads();
        const int n0 = t * 64;

        float sc[8][4];
#pragma unroll
        for (int i = 0; i < 8; i++)
#pragma unroll
            for (int j = 0; j < 4; j++) sc[i][j] = 0.0f;

#pragma unroll
        for (int ks = 0; ks < 12; ks++) {
            uint32_t afh[4], afl[4];
            {
                int row = w * 16 + a_lrow;
                int seg = ks * 2 + a_ksel;
                ldsm_x4(afh, sb + AQH + sw384(row, seg));
                ldsm_x4(afl, sb + AQL + sw384(row, seg));
            }
#pragma unroll
            for (int blk = 0; blk < 4; blk++) {
                uint32_t bh_[4], bl_[4];
                int row = blk * 16 + b_lrow;
                int seg = ks * 2 + b_ksel;
                ldsm_x4(bh_, sb + AKH + sw384(row, seg));
                ldsm_x4(bl_, sb + AKL + sw384(row, seg));
#pragma unroll
                for (int hf = 0; hf < 2; hf++) {
                    float* d = sc[blk * 2 + hf];
                    mma_bf16(d, afh, bh_[hf * 2], bh_[hf * 2 + 1]);
                    mma_bf16(d, afh, bl_[hf * 2], bl_[hf * 2 + 1]);
                    mma_bf16(d, afl, bh_[hf * 2], bh_[hf * 2 + 1]);
                }
            }
        }

        const bool diag = (t >= 2 * qti);
        const int rbase = m0 + w * 16 + (lane >> 2);
        const int cbase = n0 + (lane & 3) * 2;
#pragma unroll
        for (int a = 0; a < 2; a++) {
            float m_t = -1e30f;
#pragma unroll
            for (int nb = 0; nb < 8; nb++)
#pragma unroll
                for (int c = 0; c < 2; c++) {
                    float s = sc[nb][2 * a + c] * scale;
                    if (diag && (cbase + nb * 8 + c) > (rbase + 8 * a)) s = -1e30f;
                    sc[nb][2 * a + c] = s;
                    m_t = fmaxf(m_t, s);
                }
            m_t = fmaxf(m_t, __shfl_xor_sync(0xffffffffu, m_t, 1));
            m_t = fmaxf(m_t, __shfl_xor_sync(0xffffffffu, m_t, 2));
            float mnew = fmaxf(mi[a], m_t);
            float alpha = __expf(mi[a] - mnew);
            float rsum = 0.0f;
#pragma unroll
            for (int nb = 0; nb < 8; nb++)
#pragma unroll
                for (int c = 0; c < 2; c++) {
                    float p = __expf(sc[nb][2 * a + c] - mnew);
                    sc[nb][2 * a + c] = p;
                    rsum += p;
                }
            rsum += __shfl_xor_sync(0xffffffffu, rsum, 1);
            rsum += __shfl_xor_sync(0xffffffffu, rsum, 2);
            li[a] = li[a] * alpha + rsum;
            mi[a] = mnew;
#pragma unroll
            for (int nb2 = 0; nb2 < 16; nb2++) {
                oc[nb2][2 * a]     *= alpha;
                oc[nb2][2 * a + 1] *= alpha;
            }
        }

#pragma unroll
        for (int a = 0; a < 2; a++) {
            int row = w * 16 + (lane >> 2) + 8 * a;
#pragma unroll
            for (int nb = 0; nb < 8; nb++) {
                uint32_t hi, lo;
                split2(sc[nb][2 * a], sc[nb][2 * a + 1], hi, lo);
                uint32_t off = sw128s(row, nb) + (lane & 3) * 4;
                *(uint32_t*)(smb + APH + off) = hi;
                *(uint32_t*)(smb + APL + off) = lo;
            }
        }
        __syncwarp();
        __syncthreads();

        if (t + 1 < nk) {
#pragma unroll
            for (int i = 0; i < 6; i++) {
                int v = tid + i * 256;
                int row = v / 24, seg = v - row * 24;
                long g = ((rowbase + n0 + 64 + row) * 16 + h) * 192 + seg * 8;
                cp16(smb + AKH + sw384(row, seg), kch + g);
                cp16(smb + AKL + sw384(row, seg), kcl + g);
            }
            asm volatile("cp.async.commit_group;\n" ::: "memory");
        }

#pragma unroll
        for (int ks = 0; ks < 4; ks++) {
            uint32_t aph[4], apl[4];
            {
                int row = w * 16 + a_lrow;
                int seg = ks * 2 + a_ksel;
                ldsm_x4(aph, sb + APH + sw128s(row, seg));
                ldsm_x4(apl, sb + APL + sw128s(row, seg));
            }
#pragma unroll
            for (int blk = 0; blk < 8; blk++) {
                uint32_t bh_[4], bl_[4];
                int row = blk * 16 + b_lrow;
                int seg = ks * 2 + b_ksel;
                ldsm_x4(bh_, sb + AVH + sw128s(row, seg));
                ldsm_x4(bl_, sb + AVL + sw128s(row, seg));
#pragma unroll
                for (int hf = 0; hf < 2; hf++) {
                    float* d = oc[blk * 2 + hf];
                    mma_bf16(d, aph, bh_[hf * 2], bh_[hf * 2 + 1]);
                    mma_bf16(d, aph, bl_[hf * 2], bl_[hf * 2 + 1]);
                    mma_bf16(d, apl, bh_[hf * 2], bh_[hf * 2 + 1]);
                }
            }
        }
        __syncthreads();

        if (t + 1 < nk) {
#pragma unroll
            for (int i = 0; i < 4; i++) {
                int v = tid + i * 256;
                int row = v >> 3, seg = v & 7;
                long g = (long)(h * 128 + row) * MROWS + rowbase + n0 + 64 + seg * 8;
                cp16(smb + AVH + sw128s(row, seg), vth + g);
                cp16(smb + AVL + sw128s(row, seg), vtl + g);
            }
            asm volatile("cp.async.commit_group;\n" ::: "memory");
        }
    }

    // ---- epilogue: normalize + bf16-split store into [row][h*128+d] ----
#pragma unroll
    for (int nb2 = 0; nb2 < 16; nb2++) {
        int dcol = nb2 * 8 + (lane & 3) * 2;
#pragma unroll
        for (int a = 0; a < 2; a++) {
            long row = rowbase + m0 + w * 16 + (lane >> 2) + 8 * a;
            float inv = 1.0f / li[a];
            uint32_t hi, lo;
            split2(oc[nb2][2 * a] * inv, oc[nb2][2 * a + 1] * inv, hi, lo);
            long idx = row * DMODEL + h * HD + dcol;
            *(uint32_t*)&obh[idx] = hi;
            *(uint32_t*)&obl[idx] = lo;
        }
    }
}

// ======================= launch ============================================
#define SYM(p, s) cudaGetSymbolAddress((void**)&p, s)
#define BF16_NULL ((__nv_bfloat16*)0)

extern "C" void kernel_launch(void* const* d_in, const int* in_sizes, int n_in,
                              void* d_out, int out_size)
{
    const float* x      = (const float*)d_in[0];
    const float* w_qkv  = (const float*)d_in[1];
    const float* b_qkv  = (const float*)d_in[2];
    const float* w_qup  = (const float*)d_in[3];
    const float* b_qup  = (const float*)d_in[4];
    const float* w_kup  = (const float*)d_in[5];
    const float* b_kup  = (const float*)d_in[6];
    const float* w_vup  = (const float*)d_in[7];
    const float* b_vup  = (const float*)d_in[8];
    const float* w_qpos = (const float*)d_in[9];
    const float* b_qpos = (const float*)d_in[10];
    const float* w_kpos = (const float*)d_in[11];
    const float* b_kpos = (const float*)d_in[12];
    const float* w_o    = (const float*)d_in[13];
    const float* b_o    = (const float*)d_in[14];
    float* out = (float*)d_out;

    float *vmain, *posq, *posk, *bk128;
    SYM(vmain, g_vmain); SYM(posq, g_posq); SYM(posk, g_posk); SYM(bk128, g_bk128);
    __nv_bfloat16 *xh,*xl,*lh,*ll,*abh,*abl,*wqkvh,*wqkvl,*wkph,*wkpl,
                  *wquh,*wqul,*wkuh,*wkul,*wvuh,*wvul,*wqph,*wqpl,*woh,*wol,
                  *qch,*qcl,*kch,*kcl,*vth,*vtl;
    SYM(xh,g_xh); SYM(xl,g_xl); SYM(lh,g_lh); SYM(ll,g_ll);
    SYM(abh,g_abh); SYM(abl,g_abl);
    SYM(wqkvh,g_wqkvh); SYM(wqkvl,g_wqkvl); SYM(wkph,g_wkph); SYM(wkpl,g_wkpl);
    SYM(wquh,g_wquh); SYM(wqul,g_wqul); SYM(wkuh,g_wkuh); SYM(wkul,g_wkul);
    SYM(wvuh,g_wvuh); SYM(wvul,g_wvul); SYM(wqph,g_wqph); SYM(wqpl,g_wqpl);
    SYM(woh,g_woh); SYM(wol,g_wol);
    SYM(qch,g_qch); SYM(qcl,g_qcl); SYM(kch,g_kch); SYM(kcl,g_kcl);
    SYM(vth,g_vth); SYM(vtl,g_vtl);

    cudaFuncSetAttribute(tgemm, cudaFuncAttributeMaxDynamicSharedMemorySize, TG_SMEM);
    cudaFuncSetAttribute(attn_mma, cudaFuncAttributeMaxDynamicSharedMemorySize,
                         ATTN_SMEM);
    dim3 t8(32, 8);

    pad64<<<1, 128>>>(b_kpos, bk128);
    split_f32<<<(MROWS * DMODEL) / 256, 256>>>(x, xh, xl, MROWS * DMODEL);
    tsplit<<<dim3(1536 / 32, 2048 / 32), t8>>>(w_qkv, wqkvh, wqkvl, 2048, 1536);
    // latent -> lh/ll directly (no fp32)
    tgemm<<<dim3(12, 32), 256, TG_SMEM>>>(xh, xl, DMODEL, 0, wqkvh, wqkvl,
                                          b_qkv, (float*)0, lh, ll, 1536, DMODEL, 0);
    tsplit<<<dim3(128 / 32, 2048 / 32), t8>>>(w_kpos, wkph, wkpl, 2048, PHD);
    // posk fp32 (padded N=128), RoPE consumes it
    tgemm<<<dim3(1, 32), 256, TG_SMEM>>>(xh, xl, DMODEL, 0, wkph, wkpl,
                                         bk128, posk, BF16_NULL, BF16_NULL, 128, DMODEL, 0);
    tsplit<<<dim3(2048 / 32, 512 / 32), t8>>>(w_qup, wquh, wqul, 512, 2048);
    tsplit<<<dim3(2048 / 32, 512 / 32), t8>>>(w_kup, wkuh, wkul, 512, 2048);
    tsplit<<<dim3(2048 / 32, 512 / 32), t8>>>(w_vup, wvuh, wvul, 512, 2048);
    tsplit<<<dim3(1024 / 32, 512 / 32), t8>>>(w_qpos, wqph, wqpl, 512, 1024);
    // q/k up-proj -> directly into attention concat layout (remap)
    tgemm<<<dim3(16, 32), 256, TG_SMEM>>>(lh, ll, 1536, 0,    wquh, wqul, b_qup,
                                          (float*)0, qch, qcl, 0, LAT, 1);
    tgemm<<<dim3(16, 32), 256, TG_SMEM>>>(lh, ll, 1536, 512,  wkuh, wkul, b_kup,
                                          (float*)0, kch, kcl, 0, LAT, 1);
    // v up-proj fp32 (tsplit transposes it)
    tgemm<<<dim3(16, 32), 256, TG_SMEM>>>(lh, ll, 1536, 1024, wvuh, wvul, b_vup,
                                          vmain, BF16_NULL, BF16_NULL, DMODEL, LAT, 0);
    // posq fp32 (RoPE consumes it)
    tgemm<<<dim3(8, 32), 256, TG_SMEM>>>(lh, ll, 1536, 0,     wqph, wqpl, b_qpos,
                                         posq, BF16_NULL, BF16_NULL, 1024, LAT, 0);
    // RoPE -> bf16 split pos-columns of qch/kch
    rope_q_split<<<QROT / 256, 256>>>(posq, qch, qcl);
    rope_k_split<<<KROT / 256, 256>>>(posk, kch, kcl);
    // V transpose+split
    tsplit<<<dim3(2048 / 32, MROWS / 32), t8>>>(vmain, vth, vtl, MROWS, DMODEL);
    // attention -> abh/abl bf16 split directly
    attn_mma<<<dim3(SS / 128, BB * NHD), 256, ATTN_SMEM>>>(
        qch, qcl, kch, kcl, vth, vtl, abh, abl);
    // output projection
    tsplit<<<dim3(2048 / 32, 2048 / 32), t8>>>(w_o, woh, wol, 2048, 2048);
    tgemm<<<dim3(16, 32), 256, TG_SMEM>>>(abh, abl, DMODEL, 0, woh, wol,
                                          b_o, out, BF16_NULL, BF16_NULL, DMODEL, DMODEL, 0);
}

// round 14
// speedup vs baseline: 2.7823x; 1.0755x over previous
#include <cuda_runtime.h>
#include <cuda_bf16.h>
#include <math.h>
#include <stdint.h>

#define BB     2
#define SS     2048
#define DMODEL 2048
#define LAT    512
#define NHD    16
#define HD     128
#define PHD    64
#define DQK    192
#define MROWS  4096

// ---------------- fp32 scratch ----------------
__device__ float g_vmain [MROWS * DMODEL];
__device__ float g_posq  [MROWS * 1024];
__device__ float g_posk  [MROWS * 128];
__device__ float g_bc1   [1664];
__device__ float g_bc2   [7168];

// ---------------- bf16 split operands ----------------
__device__ __nv_bfloat16 g_xh[MROWS*DMODEL], g_xl[MROWS*DMODEL];
__device__ __nv_bfloat16 g_lh[MROWS*1536],   g_ll[MROWS*1536];
__device__ __nv_bfloat16 g_abh[MROWS*DMODEL],g_abl[MROWS*DMODEL];
// concatenated transposed weights
__device__ __nv_bfloat16 g_wc1h[1664*2048],  g_wc1l[1664*2048];   // [qkv|kpos]
__device__ __nv_bfloat16 g_wc2h[7168*512],   g_wc2l[7168*512];    // [qup|kup|vup|qpos]
__device__ __nv_bfloat16 g_woh[2048*2048],   g_wol[2048*2048];
// attention operands
__device__ __nv_bfloat16 g_qch[MROWS*16*192], g_qcl[MROWS*16*192];
__device__ __nv_bfloat16 g_kch[MROWS*16*192], g_kcl[MROWS*16*192];
__device__ __nv_bfloat16 g_vth[2048*MROWS],   g_vtl[2048*MROWS];

// ======================= helpers ===========================================
__device__ __forceinline__ uint32_t s2u(const void* p) {
    return (uint32_t)__cvta_generic_to_shared(const_cast<void*>(p));
}
__device__ __forceinline__ void cp16(void* d, const void* s) {
    asm volatile("cp.async.cg.shared.global [%0],[%1],16;\n"
                 :: "r"(s2u(d)), "l"(s) : "memory");
}
__device__ __forceinline__ void ldsm_x4(uint32_t* r, uint32_t addr) {
    asm volatile("ldmatrix.sync.aligned.m8n8.x4.shared.b16 {%0,%1,%2,%3},[%4];"
                 : "=r"(r[0]), "=r"(r[1]), "=r"(r[2]), "=r"(r[3]) : "r"(addr));
}
__device__ __forceinline__ void mma_bf16(float* d, const uint32_t* a,
                                         uint32_t b0, uint32_t b1) {
    asm volatile(
        "mma.sync.aligned.m16n8k16.row.col.f32.bf16.bf16.f32 "
        "{%0,%1,%2,%3},{%4,%5,%6,%7},{%8,%9},{%0,%1,%2,%3};"
        : "+f"(d[0]), "+f"(d[1]), "+f"(d[2]), "+f"(d[3])
        : "r"(a[0]), "r"(a[1]), "r"(a[2]), "r"(a[3]), "r"(b0), "r"(b1));
}
__device__ __forceinline__ void split2(float v0, float v1, uint32_t& hi, uint32_t& lo) {
    __nv_bfloat162 h2 = __floats2bfloat162_rn(v0, v1);
    float2 hf = __bfloat1622float2(h2);
    __nv_bfloat162 l2 = __floats2bfloat162_rn(v0 - hf.x, v1 - hf.y);
    hi = *(uint32_t*)&h2;
    lo = *(uint32_t*)&l2;
}

// ======================= shared GEMM core ==================================
#define TGSTG  65536
#define TG_SMEM (2 * TGSTG)

__device__ __forceinline__ void tg_load(
    const __nv_bfloat16* ah, const __nv_bfloat16* al,
    const __nv_bfloat16* bh, const __nv_bfloat16* bl,
    long m0, long n0, int lda, int aoff, int ldb, int kc, char* buf, int tid)
{
#pragma unroll
    for (int t4 = 0; t4 < 4; t4++) {
        const __nv_bfloat16* base = t4 == 0 ? ah : t4 == 1 ? al : t4 == 2 ? bh : bl;
        long r0 = (t4 < 2) ? m0 : n0;
        long ld = (t4 < 2) ? lda : ldb;
        int  o0 = ((t4 < 2) ? aoff : 0) + kc;
#pragma unroll
        for (int i = 0; i < 4; i++) {
            int v = tid + i * 256;
            int row = v >> 3, c16 = v & 7;
            uint32_t byte = row * 128 + c16 * 16;
            uint32_t sw = byte ^ ((byte >> 3) & 0x70);
            cp16(buf + t4 * 16384 + sw, base + (r0 + row) * ld + o0 + c16 * 8);
        }
    }
}

__device__ __forceinline__ void tg_core(
    const __nv_bfloat16* __restrict__ ah, const __nv_bfloat16* __restrict__ al,
    int lda, int aoff,
    const __nv_bfloat16* __restrict__ bth, const __nv_bfloat16* __restrict__ btl,
    long m0, long n0, int K, char* smb, float (&acc)[16][4])
{
    const int tid = threadIdx.x, wid = tid >> 5, lane = tid & 31;
    const int wm = wid & 1, wn = wid >> 1;

#pragma unroll
    for (int i = 0; i < 16; i++)
#pragma unroll
        for (int j = 0; j < 4; j++) acc[i][j] = 0.0f;

    const int nch = K >> 6;
    tg_load(ah, al, bth, btl, m0, n0, lda, aoff, K, 0, smb, tid);
    asm volatile("cp.async.commit_group;\n" ::: "memory");

    const int a_lrow = lane & 15;
    const int a_koff = (lane >> 4) * 16;
    const int b_lrow = (lane & 7) + ((lane >> 4) << 3);
    const int b_koff = ((lane >> 3) & 1) << 4;

    for (int c = 0; c < nch; c++) {
        if (c + 1 < nch) {
            tg_load(ah, al, bth, btl, m0, n0, lda, aoff, K, (c + 1) * 64,
                    smb + ((c + 1) & 1) * TGSTG, tid);
            asm volatile("cp.async.commit_group;\n" ::: "memory");
            asm volatile("cp.async.wait_group 1;\n" ::: "memory");
        } else {
            asm volatile("cp.async.wait_group 0;\n" ::: "memory");
        }
        __syncthreads();

        const uint32_t sb = s2u(smb + (c & 1) * TGSTG);

#pragma unroll
        for (int ks = 0; ks < 4; ks++) {
            uint32_t afh[4][4], afl[4][4], bfh[2][4], bfl[2][4];
            const int akb = ks * 32 + a_koff;
#pragma unroll
            for (int im = 0; im < 4; im++) {
                int row = wm * 64 + im * 16 + a_lrow;
                uint32_t off = row * 128 + (akb ^ ((row & 7) << 4));
                ldsm_x4(afh[im], sb + off);
                ldsm_x4(afl[im], sb + 16384 + off);
            }
            const int bkb = ks * 32 + b_koff;
#pragma unroll
            for (int inp = 0; inp < 2; inp++) {
                int row = wn * 32 + inp * 16 + b_lrow;
                uint32_t off = row * 128 + (bkb ^ ((row & 7) << 4));
                ldsm_x4(bfh[inp], sb + 32768 + off);
                ldsm_x4(bfl[inp], sb + 49152 + off);
            }
#pragma unroll
            for (int im = 0; im < 4; im++)
#pragma unroll
                for (int in_ = 0; in_ < 4; in_++) {
                    uint32_t h0 = bfh[in_ >> 1][(in_ & 1) * 2];
                    uint32_t h1 = bfh[in_ >> 1][(in_ & 1) * 2 + 1];
                    uint32_t l0 = bfl[in_ >> 1][(in_ & 1) * 2];
                    uint32_t l1 = bfl[in_ >> 1][(in_ & 1) * 2 + 1];
                    float* d = acc[im * 4 + in_];
                    mma_bf16(d, afh[im], h0, h1);
                    mma_bf16(d, afh[im], l0, l1);
                    mma_bf16(d, afl[im], h0, h1);
                }
        }
        __syncthreads();
    }
}

// ---- GEMM 1: [latent | posk] = x @ [w_qkv | w_kpos] -----------------------
__global__ __launch_bounds__(256, 1)
void tgemm_qkv(const __nv_bfloat16* __restrict__ xh, const __nv_bfloat16* __restrict__ xl,
               __nv_bfloat16* __restrict__ lh, __nv_bfloat16* __restrict__ ll,
               float* __restrict__ posk)
{
    extern __shared__ char smb[];
    const long m0 = blockIdx.y * 128L, n0 = blockIdx.x * 128L;
    float acc[16][4];
    tg_core(xh, xl, DMODEL, 0, g_wc1h, g_wc1l, m0, n0, DMODEL, smb, acc);

    const int tid = threadIdx.x, wid = tid >> 5, lane = tid & 31;
    const int wm = wid & 1, wn = wid >> 1;
    const long mb = m0 + wm * 64 + (lane >> 2);
    const int  nb = (int)n0 + wn * 32 + (lane & 3) * 2;
    const bool isl = n0 < 1536;
#pragma unroll
    for (int im = 0; im < 4; im++)
#pragma unroll
        for (int in_ = 0; in_ < 4; in_++) {
            const float* d = acc[im * 4 + in_];
            int col = nb + in_ * 8;
            float2 bv = *(const float2*)&g_bc1[col];
            float v00 = d[0] + bv.x, v01 = d[1] + bv.y;
            float v10 = d[2] + bv.x, v11 = d[3] + bv.y;
            long r1 = mb + im * 16, r2 = r1 + 8;
            if (isl) {
                uint32_t hi, lo;
                split2(v00, v01, hi, lo);
                *(uint32_t*)&lh[r1 * 1536 + col] = hi;
                *(uint32_t*)&ll[r1 * 1536 + col] = lo;
                split2(v10, v11, hi, lo);
                *(uint32_t*)&lh[r2 * 1536 + col] = hi;
                *(uint32_t*)&ll[r2 * 1536 + col] = lo;
            } else {
                int pc = col - 1536;
                *(float2*)&posk[r1 * 128 + pc] = make_float2(v00, v01);
                *(float2*)&posk[r2 * 128 + pc] = make_float2(v10, v11);
            }
        }
}

// ---- GEMM 2: [q|k|v|posq] up-projections, route by column range -----------
__global__ __launch_bounds__(256, 1)
void tgemm_up(const __nv_bfloat16* __restrict__ lh, const __nv_bfloat16* __restrict__ ll,
              __nv_bfloat16* __restrict__ qch, __nv_bfloat16* __restrict__ qcl,
              __nv_bfloat16* __restrict__ kch, __nv_bfloat16* __restrict__ kcl,
              float* __restrict__ vmain, float* __restrict__ posq)
{
    extern __shared__ char smb[];
    const long m0 = blockIdx.y * 128L, n0 = blockIdx.x * 128L;
    const int route = (int)(n0 >> 11);                 // 0:q 1:k 2:v 3:posq
    const int aoff  = (route == 1) ? 512 : (route == 2) ? 1024 : 0;
    float acc[16][4];
    tg_core(lh, ll, 1536, aoff, g_wc2h, g_wc2l, m0, n0, LAT, smb, acc);

    const int tid = threadIdx.x, wid = tid >> 5, lane = tid & 31;
    const int wm = wid & 1, wn = wid >> 1;
    const long mb = m0 + wm * 64 + (lane >> 2);
    const int  nb = (int)n0 + wn * 32 + (lane & 3) * 2;
#pragma unroll
    for (int im = 0; im < 4; im++)
#pragma unroll
        for (int in_ = 0; in_ < 4; in_++) {
            const float* d = acc[im * 4 + in_];
            int col = nb + in_ * 8;
            float2 bv = *(const float2*)&g_bc2[col];
            float v00 = d[0] + bv.x, v01 = d[1] + bv.y;
            float v10 = d[2] + bv.x, v11 = d[3] + bv.y;
            long r1 = mb + im * 16, r2 = r1 + 8;
            if (route < 2) {
                int lc = col & 2047;
                long o = (long)(lc >> 7) * 192 + (lc & 127);
                __nv_bfloat16* oh = route == 0 ? qch : kch;
                __nv_bfloat16* ol = route == 0 ? qcl : kcl;
                uint32_t hi, lo;
                split2(v00, v01, hi, lo);
                *(uint32_t*)&oh[r1 * 3072 + o] = hi;
                *(uint32_t*)&ol[r1 * 3072 + o] = lo;
                split2(v10, v11, hi, lo);
                *(uint32_t*)&oh[r2 * 3072 + o] = hi;
                *(uint32_t*)&ol[r2 * 3072 + o] = lo;
            } else if (route == 2) {
                int vc = col - 4096;
                *(float2*)&vmain[r1 * DMODEL + vc] = make_float2(v00, v01);
                *(float2*)&vmain[r2 * DMODEL + vc] = make_float2(v10, v11);
            } else {
                int pc = col - 6144;
                *(float2*)&posq[r1 * 1024 + pc] = make_float2(v00, v01);
                *(float2*)&posq[r2 * 1024 + pc] = make_float2(v10, v11);
            }
        }
}

// ---- GEMM 3: generic (w_o) -------------------------------------------------
__global__ __launch_bounds__(256, 1)
void tgemm(const __nv_bfloat16* __restrict__ ah, const __nv_bfloat16* __restrict__ al,
           int lda,
           const __nv_bfloat16* __restrict__ bth, const __nv_bfloat16* __restrict__ btl,
           const float* __restrict__ bias, float* __restrict__ Cf, int ldc, int K)
{
    extern __shared__ char smb[];
    const long m0 = blockIdx.y * 128L, n0 = blockIdx.x * 128L;
    float acc[16][4];
    tg_core(ah, al, lda, 0, bth, btl, m0, n0, K, smb, acc);

    const int tid = threadIdx.x, wid = tid >> 5, lane = tid & 31;
    const int wm = wid & 1, wn = wid >> 1;
    const long mb = m0 + wm * 64 + (lane >> 2);
    const int  nb = (int)n0 + wn * 32 + (lane & 3) * 2;
#pragma unroll
    for (int im = 0; im < 4; im++)
#pragma unroll
        for (int in_ = 0; in_ < 4; in_++) {
            const float* d = acc[im * 4 + in_];
            int col = nb + in_ * 8;
            float2 bv = *(const float2*)&bias[col];
            long r1 = mb + im * 16, r2 = r1 + 8;
            *(float2*)&Cf[r1 * (long)ldc + col] = make_float2(d[0] + bv.x, d[1] + bv.y);
            *(float2*)&Cf[r2 * (long)ldc + col] = make_float2(d[2] + bv.x, d[3] + bv.y);
        }
}

// ======================= conversion kernels ================================
__global__ void split_f32(const float* __restrict__ s, __nv_bfloat16* __restrict__ h,
                          __nv_bfloat16* __restrict__ l, int n)
{
    int i = blockIdx.x * 256 + threadIdx.x;
    if (i >= n) return;
    float v = s[i];
    __nv_bfloat16 hv = __float2bfloat16(v);
    h[i] = hv;
    l[i] = __float2bfloat16(v - __bfloat162float(hv));
}

__device__ __forceinline__ void tsplit_body(
    const float* __restrict__ w, __nv_bfloat16* __restrict__ th,
    __nv_bfloat16* __restrict__ tl, int K, int N, int bx, int by)
{
    __shared__ float t[32][33];
    int nb = bx * 32, kb = by * 32;
    for (int r = threadIdx.y; r < 32; r += 8) {
        int n = nb + threadIdx.x;
        t[r][threadIdx.x] = (n < N) ? w[(long)(kb + r) * N + n] : 0.0f;
    }
    __syncthreads();
    for (int r = threadIdx.y; r < 32; r += 8) {
        long n = nb + r, k = kb + threadIdx.x;
        float v = t[threadIdx.x][r];
        __nv_bfloat16 hv = __float2bfloat16(v);
        th[n * K + k] = hv;
        tl[n * K + k] = __float2bfloat16(v - __bfloat162float(hv));
    }
}

__global__ void tsplit(const float* __restrict__ w, __nv_bfloat16* __restrict__ th,
                       __nv_bfloat16* __restrict__ tl, int K, int N)
{
    tsplit_body(w, th, tl, K, N, blockIdx.x, blockIdx.y);
}

// all weight transposes in one launch
#define TS_J0 3072                 // w_qkv  (48 x 64), K=2048, N=1536 -> wc1[0]
#define TS_J1 (TS_J0 + 256)        // w_kpos ( 4 x 64), K=2048, N=64   -> wc1[1536]
#define TS_J2 (TS_J1 + 1024)       // w_qup  (64 x 16), K=512,  N=2048 -> wc2[0]
#define TS_J3 (TS_J2 + 1024)       // w_kup                           -> wc2[2048]
#define TS_J4 (TS_J3 + 1024)       // w_vup                           -> wc2[4096]
#define TS_J5 (TS_J4 + 512)        // w_qpos (32 x 16), K=512, N=1024 -> wc2[6144]
#define TS_TOT (TS_J5 + 4096)      // w_o    (64 x 64), K=2048, N=2048 -> woh

__global__ void tsplit_all(const float* __restrict__ wqkv, const float* __restrict__ wkp,
                           const float* __restrict__ wqu, const float* __restrict__ wku,
                           const float* __restrict__ wvu, const float* __restrict__ wqp,
                           const float* __restrict__ wo)
{
    int bid = blockIdx.x;
    const float* src; __nv_bfloat16 *th, *tl; int K, N, nbx, rb;
    if (bid < TS_J0)      { src = wqkv; th = g_wc1h;              tl = g_wc1l;              K = 2048; N = 1536; nbx = 48; rb = bid; }
    else if (bid < TS_J1) { src = wkp;  th = g_wc1h + 1536*2048;  tl = g_wc1l + 1536*2048;  K = 2048; N = 64;   nbx = 4;  rb = bid - TS_J0; }
    else if (bid < TS_J2) { src = wqu;  th = g_wc2h;              tl = g_wc2l;              K = 512;  N = 2048; nbx = 64; rb = bid - TS_J1; }
    else if (bid < TS_J3) { src = wku;  th = g_wc2h + 2048*512;   tl = g_wc2l + 2048*512;   K = 512;  N = 2048; nbx = 64; rb = bid - TS_J2; }
    else if (bid < TS_J4) { src = wvu;  th = g_wc2h + 4096*512;   tl = g_wc2l + 4096*512;   K = 512;  N = 2048; nbx = 64; rb = bid - TS_J3; }
    else if (bid < TS_J5) { src = wqp;  th = g_wc2h + 6144*512;   tl = g_wc2l + 6144*512;   K = 512;  N = 1024; nbx = 32; rb = bid - TS_J4; }
    else                  { src = wo;   th = g_woh;               tl = g_wol;               K = 2048; N = 2048; nbx = 64; rb = bid - TS_J5; }
    tsplit_body(src, th, tl, K, N, rb % nbx, rb / nbx);
}

__global__ void build_biases(const float* __restrict__ bqkv, const float* __restrict__ bkpos,
                             const float* __restrict__ bqup, const float* __restrict__ bkup,
                             const float* __restrict__ bvup, const float* __restrict__ bqpos)
{
    int i = blockIdx.x * 256 + threadIdx.x;
    if (i < 1664)
        g_bc1[i] = i < 1536 ? bqkv[i] : ((i - 1536) < 64 ? bkpos[i - 1536] : 0.0f);
    if (i < 7168) {
        int r = i >> 11, c = i & 2047;
        g_bc2[i] = r == 0 ? bqup[c] : r == 1 ? bkup[c] : r == 2 ? bvup[c] : bqpos[i - 6144];
    }
}

// ======================= fused RoPE -> bf16 split ==========================
#define LOG2_THETA_OVER_32 0.48780126482613787f
#define QROT (MROWS * 512)
#define KROT (MROWS * 32)

__global__ void rope_q_split(const float* __restrict__ pq,
                             __nv_bfloat16* __restrict__ qh, __nv_bfloat16* __restrict__ ql)
{
    int idx = blockIdx.x * 256 + threadIdx.x;
    if (idx >= QROT) return;
    int r = idx >> 9, rem = idx & 511, h = rem >> 5, i = rem & 31;
    int s = r & (SS - 1);
    float ang = (float)s * exp2f(-(float)i * LOG2_THETA_OVER_32);
    float sn, cs; sincosf(ang, &sn, &cs);
    float v0 = pq[(long)r * 1024 + h * 64 + i];
    float v1 = pq[(long)r * 1024 + h * 64 + i + 32];
    float y0 = v0 * cs - v1 * sn;
    float y1 = v1 * cs + v0 * sn;
    long base = (long)r * 3072 + h * 192 + 128 + i;
    __nv_bfloat16 h0 = __float2bfloat16(y0);
    __nv_bfloat16 h1 = __float2bfloat16(y1);
    qh[base]      = h0;  ql[base]      = __float2bfloat16(y0 - __bfloat162float(h0));
    qh[base + 32] = h1;  ql[base + 32] = __float2bfloat16(y1 - __bfloat162float(h1));
}

__global__ void rope_k_split(const float* __restrict__ pk,
                             __nv_bfloat16* __restrict__ kh, __nv_bfloat16* __restrict__ kl)
{
    int idx = blockIdx.x * 256 + threadIdx.x;
    if (idx >= KROT) return;
    int r = idx >> 5, i = idx & 31;
    int s = r & (SS - 1);
    float ang = (float)s * exp2f(-(float)i * LOG2_THETA_OVER_32);
    float sn, cs; sincosf(ang, &sn, &cs);
    float v0 = pk[(long)r * 128 + i];
    float v1 = pk[(long)r * 128 + i + 32];
    float y0 = v0 * cs - v1 * sn;
    float y1 = v1 * cs + v0 * sn;
    __nv_bfloat16 h0 = __float2bfloat16(y0);
    __nv_bfloat16 h1 = __float2bfloat16(y1);
    __nv_bfloat16 l0 = __float2bfloat16(y0 - __bfloat162float(h0));
    __nv_bfloat16 l1 = __float2bfloat16(y1 - __bfloat162float(h1));
    long rb = (long)r * 3072 + 128 + i;
#pragma unroll
    for (int h = 0; h < 16; h++) {
        kh[rb + h * 192]      = h0;  kl[rb + h * 192]      = l0;
        kh[rb + h * 192 + 32] = h1;  kl[rb + h * 192 + 32] = l1;
    }
}

// ======================= tensor-core flash attention =======================
#define AQH 0
#define AQL 49152
#define AKH 98304
#define AKL 122880
#define AVH 147456
#define AVL 163840
#define APH 180224
#define APL 196608
#define ATTN_SMEM 212992

__device__ __forceinline__ uint32_t sw384(int row, int seg) {
    return row * 384 + (((seg & 24) | ((seg ^ row) & 7)) << 4);
}
__device__ __forceinline__ uint32_t sw128s(int row, int seg) {
    return row * 128 + (((seg ^ row) & 7) << 4);
}

__global__ __launch_bounds__(256, 1)
void attn_mma(const __nv_bfloat16* __restrict__ qch, const __nv_bfloat16* __restrict__ qcl,
              const __nv_bfloat16* __restrict__ kch, const __nv_bfloat16* __restrict__ kcl,
              const __nv_bfloat16* __restrict__ vth, const __nv_bfloat16* __restrict__ vtl,
              __nv_bfloat16* __restrict__ obh, __nv_bfloat16* __restrict__ obl)
{
    extern __shared__ char smb[];
    const uint32_t sb = s2u(smb);
    const int tid = threadIdx.x, lane = tid & 31, w = tid >> 5;
    const int bh = blockIdx.y, b = bh >> 4, h = bh & 15;
    const int qti = (int)gridDim.x - 1 - (int)blockIdx.x;
    const int m0 = qti * 128, nk = 2 * qti + 2;
    const long rowbase = (long)b * SS;
    const float scale = 0.07216878364870323f;

#pragma unroll
    for (int i = 0; i < 12; i++) {
        int v = tid + i * 256;
        int row = v / 24, seg = v - row * 24;
        long g = ((rowbase + m0 + row) * 16 + h) * 192 + seg * 8;
        cp16(smb + AQH + sw384(row, seg), qch + g);
        cp16(smb + AQL + sw384(row, seg), qcl + g);
    }
#pragma unroll
    for (int i = 0; i < 6; i++) {
        int v = tid + i * 256;
        int row = v / 24, seg = v - row * 24;
        long g = ((rowbase + row) * 16 + h) * 192 + seg * 8;
        cp16(smb + AKH + sw384(row, seg), kch + g);
        cp16(smb + AKL + sw384(row, seg), kcl + g);
    }
#pragma unroll
    for (int i = 0; i < 4; i++) {
        int v = tid + i * 256;
        int row = v >> 3, seg = v & 7;
        long g = (long)(h * 128 + row) * MROWS + rowbase + seg * 8;
        cp16(smb + AVH + sw128s(row, seg), vth + g);
        cp16(smb + AVL + sw128s(row, seg), vtl + g);
    }
    asm volatile("cp.async.commit_group;\n" ::: "memory");

    float oc[16][4];
#pragma unroll
    for (int i = 0; i < 16; i++)
#pragma unroll
        for (int j = 0; j < 4; j++) oc[i][j] = 0.0f;
    float mi[2] = {-1e30f, -1e30f}, li[2] = {0.0f, 0.0f};

    const int a_lrow = lane & 15;
    const int a_ksel = lane >> 4;
    const int b_lrow = (lane & 7) + ((lane >> 4) << 3);
    const int b_ksel = (lane >> 3) & 1;

    for (int t = 0; t < nk; ++t) {
        asm volatile("cp.async.wait_group 0;\n" ::: "memory");
        __syncthreads();
        const int n0 = t * 64;

        float sc[8][4];
#pragma unroll
        for (int i = 0; i < 8; i++)
#pragma unroll
            for (int j = 0; j < 4; j++) sc[i][j] = 0.0f;

#pragma unroll
        for (int ks = 0; ks < 12; ks++) {
            uint32_t afh[4], afl[4];
            {
                int row = w * 16 + a_lrow;
                int seg = ks * 2 + a_ksel;
                ldsm_x4(afh, sb + AQH + sw384(row, seg));
                ldsm_x4(afl, sb + AQL + sw384(row, seg));
            }
#pragma unroll
            for (int blk = 0; blk < 4; blk++) {
                uint32_t bh_[4], bl_[4];
                int row = blk * 16 + b_lrow;
                int seg = ks * 2 + b_ksel;
                ldsm_x4(bh_, sb + AKH + sw384(row, seg));
                ldsm_x4(bl_, sb + AKL + sw384(row, seg));
#pragma unroll
                for (int hf = 0; hf < 2; hf++) {
                    float* d = sc[blk * 2 + hf];
                    mma_bf16(d, afh, bh_[hf * 2], bh_[hf * 2 + 1]);
                    mma_bf16(d, afh, bl_[hf * 2], bl_[hf * 2 + 1]);
                    mma_bf16(d, afl, bh_[hf * 2], bh_[hf * 2 + 1]);
                }
            }
        }

        const bool diag = (t >= 2 * qti);
        const int rbase = m0 + w * 16 + (lane >> 2);
        const int cbase = n0 + (lane & 3) * 2;
#pragma unroll
        for (int a = 0; a < 2; a++) {
            float m_t = -1e30f;
#pragma unroll
            for (int nb = 0; nb < 8; nb++)
#pragma unroll
                for (int c = 0; c < 2; c++) {
                    float s = sc[nb][2 * a + c] * scale;
                    if (diag && (cbase + nb * 8 + c) > (rbase + 8 * a)) s = -1e30f;
                    sc[nb][2 * a + c] = s;
                    m_t = fmaxf(m_t, s);
                }
            m_t = fmaxf(m_t, __shfl_xor_sync(0xffffffffu, m_t, 1));
            m_t = fmaxf(m_t, __shfl_xor_sync(0xffffffffu, m_t, 2));
            float mnew = fmaxf(mi[a], m_t);
            float alpha = __expf(mi[a] - mnew);
            float rsum = 0.0f;
#pragma unroll
            for (int nb = 0; nb < 8; nb++)
#pragma unroll
                for (int c = 0; c < 2; c++) {
                    float p = __expf(sc[nb][2 * a + c] - mnew);
                    sc[nb][2 * a + c] = p;
                    rsum += p;
                }
            rsum += __shfl_xor_sync(0xffffffffu, rsum, 1);
            rsum += __shfl_xor_sync(0xffffffffu, rsum, 2);
            li[a] = li[a] * alpha + rsum;
            mi[a] = mnew;
#pragma unroll
            for (int nb2 = 0; nb2 < 16; nb2++) {
                oc[nb2][2 * a]     *= alpha;
                oc[nb2][2 * a + 1] *= alpha;
            }
        }

#pragma unroll
        for (int a = 0; a < 2; a++) {
            int row = w * 16 + (lane >> 2) + 8 * a;
#pragma unroll
            for (int nb = 0; nb < 8; nb++) {
                uint32_t hi, lo;
                split2(sc[nb][2 * a], sc[nb][2 * a + 1], hi, lo);
                uint32_t off = sw128s(row, nb) + (lane & 3) * 4;
                *(uint32_t*)(smb + APH + off) = hi;
                *(uint32_t*)(smb + APL + off) = lo;
            }
        }
        __syncwarp();
        __syncthreads();

        if (t + 1 < nk) {
#pragma unroll
            for (int i = 0; i < 6; i++) {
                int v = tid + i * 256;
                int row = v / 24, seg = v - row * 24;
                long g = ((rowbase + n0 + 64 + row) * 16 + h) * 192 + seg * 8;
                cp16(smb + AKH + sw384(row, seg), kch + g);
                cp16(smb + AKL + sw384(row, seg), kcl + g);
            }
            asm volatile("cp.async.commit_group;\n" ::: "memory");
        }

#pragma unroll
        for (int ks = 0; ks < 4; ks++) {
            uint32_t aph[4], apl[4];
            {
                int row = w * 16 + a_lrow;
                int seg = ks * 2 + a_ksel;
                ldsm_x4(aph, sb + APH + sw128s(row, seg));
                ldsm_x4(apl, sb + APL + sw128s(row, seg));
            }
#pragma unroll
            for (int blk = 0; blk < 8; blk++) {
                uint32_t bh_[4], bl_[4];
                int row = blk * 16 + b_lrow;
                int seg = ks * 2 + b_ksel;
                ldsm_x4(bh_, sb + AVH + sw128s(row, seg));
                ldsm_x4(bl_, sb + AVL + sw128s(row, seg));
#pragma unroll
                for (int hf = 0; hf < 2; hf++) {
                    float* d = oc[blk * 2 + hf];
                    mma_bf16(d, aph, bh_[hf * 2], bh_[hf * 2 + 1]);
                    mma_bf16(d, aph, bl_[hf * 2], bl_[hf * 2 + 1]);
                    mma_bf16(d, apl, bh_[hf * 2], bh_[hf * 2 + 1]);
                }
            }
        }
        __syncthreads();

        if (t + 1 < nk) {
#pragma unroll
            for (int i = 0; i < 4; i++) {
                int v = tid + i * 256;
                int row = v >> 3, seg = v & 7;
                long g = (long)(h * 128 + row) * MROWS + rowbase + n0 + 64 + seg * 8;
                cp16(smb + AVH + sw128s(row, seg), vth + g);
                cp16(smb + AVL + sw128s(row, seg), vtl + g);
            }
            asm volatile("cp.async.commit_group;\n" ::: "memory");
        }
    }

#pragma unroll
    for (int nb2 = 0; nb2 < 16; nb2++) {
        int dcol = nb2 * 8 + (lane & 3) * 2;
#pragma unroll
        for (int a = 0; a < 2; a++) {
            long row = rowbase + m0 + w * 16 + (lane >> 2) + 8 * a;
            float inv = 1.0f / li[a];
            uint32_t hi, lo;
            split2(oc[nb2][2 * a] * inv, oc[nb2][2 * a + 1] * inv, hi, lo);
            long idx = row * DMODEL + h * HD + dcol;
            *(uint32_t*)&obh[idx] = hi;
            *(uint32_t*)&obl[idx] = lo;
        }
    }
}

// ======================= launch ============================================
#define SYM(p, s) cudaGetSymbolAddress((void**)&p, s)

extern "C" void kernel_launch(void* const* d_in, const int* in_sizes, int n_in,
                              void* d_out, int out_size)
{
    const float* x      = (const float*)d_in[0];
    const float* w_qkv  = (const float*)d_in[1];
    const float* b_qkv  = (const float*)d_in[2];
    const float* w_qup  = (const float*)d_in[3];
    const float* b_qup  = (const float*)d_in[4];
    const float* w_kup  = (const float*)d_in[5];
    const float* b_kup  = (const float*)d_in[6];
    const float* w_vup  = (const float*)d_in[7];
    const float* b_vup  = (const float*)d_in[8];
    const float* w_qpos = (const float*)d_in[9];
    const float* b_qpos = (const float*)d_in[10];
    const float* w_kpos = (const float*)d_in[11];
    const float* b_kpos = (const float*)d_in[12];
    const float* w_o    = (const float*)d_in[13];
    const float* b_o    = (const float*)d_in[14];
    float* out = (float*)d_out;

    float *vmain, *posq, *posk;
    SYM(vmain, g_vmain); SYM(posq, g_posq); SYM(posk, g_posk);
    __nv_bfloat16 *xh,*xl,*lh,*ll,*abh,*abl,*woh,*wol,
                  *qch,*qcl,*kch,*kcl,*vth,*vtl;
    SYM(xh,g_xh); SYM(xl,g_xl); SYM(lh,g_lh); SYM(ll,g_ll);
    SYM(abh,g_abh); SYM(abl,g_abl);
    SYM(woh,g_woh); SYM(wol,g_wol);
    SYM(qch,g_qch); SYM(qcl,g_qcl); SYM(kch,g_kch); SYM(kcl,g_kcl);
    SYM(vth,g_vth); SYM(vtl,g_vtl);

    cudaFuncSetAttribute(tgemm_qkv, cudaFuncAttributeMaxDynamicSharedMemorySize, TG_SMEM);
    cudaFuncSetAttribute(tgemm_up,  cudaFuncAttributeMaxDynamicSharedMemorySize, TG_SMEM);
    cudaFuncSetAttribute(tgemm,     cudaFuncAttributeMaxDynamicSharedMemorySize, TG_SMEM);
    cudaFuncSetAttribute(attn_mma,  cudaFuncAttributeMaxDynamicSharedMemorySize, ATTN_SMEM);
    dim3 t8(32, 8);

    // 1) all weight transposes, one launch
    tsplit_all<<<TS_TOT, t8>>>(w_qkv, w_kpos, w_qup, w_kup, w_vup, w_qpos, w_o);
    // 2) concatenated biases
    build_biases<<<28, 256>>>(b_qkv, b_kpos, b_qup, b_kup, b_vup, b_qpos);
    // 3) split x
    split_f32<<<(MROWS * DMODEL) / 256, 256>>>(x, xh, xl, MROWS * DMODEL);
    // 4) [latent | posk] = x @ wc1
    tgemm_qkv<<<dim3(13, 32), 256, TG_SMEM>>>(xh, xl, lh, ll, posk);
    // 5) [q|k|v|posq] = latent-slices @ wc2 (routed)
    tgemm_up<<<dim3(56, 32), 256, TG_SMEM>>>(lh, ll, qch, qcl, kch, kcl, vmain, posq);
    // 6-7) RoPE -> bf16 split pos-columns
    rope_q_split<<<QROT / 256, 256>>>(posq, qch, qcl);
    rope_k_split<<<KROT / 256, 256>>>(posk, kch, kcl);
    // 8) V transpose+split
    tsplit<<<dim3(2048 / 32, MROWS / 32), t8>>>(vmain, vth, vtl, MROWS, DMODEL);
    // 9) attention
    attn_mma<<<dim3(SS / 128, BB * NHD), 256, ATTN_SMEM>>>(
        qch, qcl, kch, kcl, vth, vtl, abh, abl);
    // 10) out = attn @ w_o
    tgemm<<<dim3(16, 32), 256, TG_SMEM>>>(abh, abl, DMODEL, woh, wol,
                                          b_o, out, DMODEL, DMODEL);
}

// round 15
// speedup vs baseline: 2.7827x; 1.0001x over previous
#include <cuda_runtime.h>
#include <cuda_bf16.h>
#include <math.h>
#include <stdint.h>

#define BB     2
#define SS     2048
#define DMODEL 2048
#define LAT    512
#define NHD    16
#define HD     128
#define PHD    64
#define DQK    192
#define MROWS  4096

// ---------------- fp32 scratch ----------------
__device__ float g_vmain [MROWS * DMODEL];
__device__ float g_posq  [MROWS * 1024];
__device__ float g_posk  [MROWS * 128];
__device__ float g_bc1   [1664];
__device__ float g_bc2   [7168];

// ---------------- bf16 split operands ----------------
__device__ __nv_bfloat16 g_xh[MROWS*DMODEL], g_xl[MROWS*DMODEL];
__device__ __nv_bfloat16 g_lh[MROWS*1536],   g_ll[MROWS*1536];
__device__ __nv_bfloat16 g_abh[MROWS*DMODEL],g_abl[MROWS*DMODEL];
// concatenated transposed weights
__device__ __nv_bfloat16 g_wc1h[1664*2048],  g_wc1l[1664*2048];   // [qkv|kpos]
__device__ __nv_bfloat16 g_wc2h[7168*512],   g_wc2l[7168*512];    // [qup|kup|vup|qpos]
__device__ __nv_bfloat16 g_woh[2048*2048],   g_wol[2048*2048];
// attention operands
__device__ __nv_bfloat16 g_qch[MROWS*16*192], g_qcl[MROWS*16*192];
__device__ __nv_bfloat16 g_kch[MROWS*16*192], g_kcl[MROWS*16*192];
__device__ __nv_bfloat16 g_vth[2048*MROWS],   g_vtl[2048*MROWS];

// ======================= helpers ===========================================
__device__ __forceinline__ uint32_t s2u(const void* p) {
    return (uint32_t)__cvta_generic_to_shared(const_cast<void*>(p));
}
__device__ __forceinline__ void cp16(void* d, const void* s) {
    asm volatile("cp.async.cg.shared.global [%0],[%1],16;\n"
                 :: "r"(s2u(d)), "l"(s) : "memory");
}
__device__ __forceinline__ void ldsm_x4(uint32_t* r, uint32_t addr) {
    asm volatile("ldmatrix.sync.aligned.m8n8.x4.shared.b16 {%0,%1,%2,%3},[%4];"
                 : "=r"(r[0]), "=r"(r[1]), "=r"(r[2]), "=r"(r[3]) : "r"(addr));
}
__device__ __forceinline__ void mma_bf16(float* d, const uint32_t* a,
                                         uint32_t b0, uint32_t b1) {
    asm volatile(
        "mma.sync.aligned.m16n8k16.row.col.f32.bf16.bf16.f32 "
        "{%0,%1,%2,%3},{%4,%5,%6,%7},{%8,%9},{%0,%1,%2,%3};"
        : "+f"(d[0]), "+f"(d[1]), "+f"(d[2]), "+f"(d[3])
        : "r"(a[0]), "r"(a[1]), "r"(a[2]), "r"(a[3]), "r"(b0), "r"(b1));
}
__device__ __forceinline__ void split2(float v0, float v1, uint32_t& hi, uint32_t& lo) {
    __nv_bfloat162 h2 = __floats2bfloat162_rn(v0, v1);
    float2 hf = __bfloat1622float2(h2);
    __nv_bfloat162 l2 = __floats2bfloat162_rn(v0 - hf.x, v1 - hf.y);
    hi = *(uint32_t*)&h2;
    lo = *(uint32_t*)&l2;
}

// ======================= shared GEMM core ==================================
#define TGSTG  65536
#define TG_SMEM (2 * TGSTG)

__device__ __forceinline__ void tg_load(
    const __nv_bfloat16* ah, const __nv_bfloat16* al,
    const __nv_bfloat16* bh, const __nv_bfloat16* bl,
    long m0, long n0, int lda, int aoff, int ldb, int kc, char* buf, int tid)
{
#pragma unroll
    for (int t4 = 0; t4 < 4; t4++) {
        const __nv_bfloat16* base = t4 == 0 ? ah : t4 == 1 ? al : t4 == 2 ? bh : bl;
        long r0 = (t4 < 2) ? m0 : n0;
        long ld = (t4 < 2) ? lda : ldb;
        int  o0 = ((t4 < 2) ? aoff : 0) + kc;
#pragma unroll
        for (int i = 0; i < 4; i++) {
            int v = tid + i * 256;
            int row = v >> 3, c16 = v & 7;
            uint32_t byte = row * 128 + c16 * 16;
            uint32_t sw = byte ^ ((byte >> 3) & 0x70);
            cp16(buf + t4 * 16384 + sw, base + (r0 + row) * ld + o0 + c16 * 8);
        }
    }
}

// fragment load for one 16-wide k-step
__device__ __forceinline__ void tg_frag_load(
    uint32_t sb, int wm, int wn, int ks,
    int a_lrow, int a_koff, int b_lrow, int b_koff,
    uint32_t (&afh)[4][4], uint32_t (&afl)[4][4],
    uint32_t (&bfh)[2][4], uint32_t (&bfl)[2][4])
{
    const int akb = ks * 32 + a_koff;
#pragma unroll
    for (int im = 0; im < 4; im++) {
        int row = wm * 64 + im * 16 + a_lrow;
        uint32_t off = row * 128 + (akb ^ ((row & 7) << 4));
        ldsm_x4(afh[im], sb + off);
        ldsm_x4(afl[im], sb + 16384 + off);
    }
    const int bkb = ks * 32 + b_koff;
#pragma unroll
    for (int inp = 0; inp < 2; inp++) {
        int row = wn * 32 + inp * 16 + b_lrow;
        uint32_t off = row * 128 + (bkb ^ ((row & 7) << 4));
        ldsm_x4(bfh[inp], sb + 32768 + off);
        ldsm_x4(bfl[inp], sb + 49152 + off);
    }
}

__device__ __forceinline__ void tg_core(
    const __nv_bfloat16* __restrict__ ah, const __nv_bfloat16* __restrict__ al,
    int lda, int aoff,
    const __nv_bfloat16* __restrict__ bth, const __nv_bfloat16* __restrict__ btl,
    long m0, long n0, int K, char* smb, float (&acc)[16][4])
{
    const int tid = threadIdx.x, wid = tid >> 5, lane = tid & 31;
    const int wm = wid & 1, wn = wid >> 1;

#pragma unroll
    for (int i = 0; i < 16; i++)
#pragma unroll
        for (int j = 0; j < 4; j++) acc[i][j] = 0.0f;

    const int nch = K >> 6;
    tg_load(ah, al, bth, btl, m0, n0, lda, aoff, K, 0, smb, tid);
    asm volatile("cp.async.commit_group;\n" ::: "memory");

    const int a_lrow = lane & 15;
    const int a_koff = (lane >> 4) * 16;
    const int b_lrow = (lane & 7) + ((lane >> 4) << 3);
    const int b_koff = ((lane >> 3) & 1) << 4;

    // double-buffered fragment registers (pipeline ldsm ahead of mma)
    uint32_t afh[2][4][4], afl[2][4][4], bfh[2][2][4], bfl[2][2][4];

    for (int c = 0; c < nch; c++) {
        if (c + 1 < nch) {
            tg_load(ah, al, bth, btl, m0, n0, lda, aoff, K, (c + 1) * 64,
                    smb + ((c + 1) & 1) * TGSTG, tid);
            asm volatile("cp.async.commit_group;\n" ::: "memory");
            asm volatile("cp.async.wait_group 1;\n" ::: "memory");
        } else {
            asm volatile("cp.async.wait_group 0;\n" ::: "memory");
        }
        __syncthreads();

        const uint32_t sb = s2u(smb + (c & 1) * TGSTG);

        tg_frag_load(sb, wm, wn, 0, a_lrow, a_koff, b_lrow, b_koff,
                     afh[0], afl[0], bfh[0], bfl[0]);
#pragma unroll
        for (int ks = 0; ks < 4; ks++) {
            const int cur = ks & 1;
            if (ks < 3)
                tg_frag_load(sb, wm, wn, ks + 1, a_lrow, a_koff, b_lrow, b_koff,
                             afh[cur ^ 1], afl[cur ^ 1], bfh[cur ^ 1], bfl[cur ^ 1]);
#pragma unroll
            for (int im = 0; im < 4; im++)
#pragma unroll
                for (int in_ = 0; in_ < 4; in_++) {
                    uint32_t h0 = bfh[cur][in_ >> 1][(in_ & 1) * 2];
                    uint32_t h1 = bfh[cur][in_ >> 1][(in_ & 1) * 2 + 1];
                    uint32_t l0 = bfl[cur][in_ >> 1][(in_ & 1) * 2];
                    uint32_t l1 = bfl[cur][in_ >> 1][(in_ & 1) * 2 + 1];
                    float* d = acc[im * 4 + in_];
                    mma_bf16(d, afh[cur][im], h0, h1);
                    mma_bf16(d, afh[cur][im], l0, l1);
                    mma_bf16(d, afl[cur][im], h0, h1);
                }
        }
        __syncthreads();
    }
}

// ---- GEMM 1: [latent | posk] = x @ [w_qkv | w_kpos] -----------------------
__global__ __launch_bounds__(256, 1)
void tgemm_qkv(const __nv_bfloat16* __restrict__ xh, const __nv_bfloat16* __restrict__ xl,
               __nv_bfloat16* __restrict__ lh, __nv_bfloat16* __restrict__ ll,
               float* __restrict__ posk)
{
    extern __shared__ char smb[];
    const long m0 = blockIdx.y * 128L, n0 = blockIdx.x * 128L;
    float acc[16][4];
    tg_core(xh, xl, DMODEL, 0, g_wc1h, g_wc1l, m0, n0, DMODEL, smb, acc);

    const int tid = threadIdx.x, wid = tid >> 5, lane = tid & 31;
    const int wm = wid & 1, wn = wid >> 1;
    const long mb = m0 + wm * 64 + (lane >> 2);
    const int  nb = (int)n0 + wn * 32 + (lane & 3) * 2;
    const bool isl = n0 < 1536;
#pragma unroll
    for (int im = 0; im < 4; im++)
#pragma unroll
        for (int in_ = 0; in_ < 4; in_++) {
            const float* d = acc[im * 4 + in_];
            int col = nb + in_ * 8;
            float2 bv = *(const float2*)&g_bc1[col];
            float v00 = d[0] + bv.x, v01 = d[1] + bv.y;
            float v10 = d[2] + bv.x, v11 = d[3] + bv.y;
            long r1 = mb + im * 16, r2 = r1 + 8;
            if (isl) {
                uint32_t hi, lo;
                split2(v00, v01, hi, lo);
                *(uint32_t*)&lh[r1 * 1536 + col] = hi;
                *(uint32_t*)&ll[r1 * 1536 + col] = lo;
                split2(v10, v11, hi, lo);
                *(uint32_t*)&lh[r2 * 1536 + col] = hi;
                *(uint32_t*)&ll[r2 * 1536 + col] = lo;
            } else {
                int pc = col - 1536;
                *(float2*)&posk[r1 * 128 + pc] = make_float2(v00, v01);
                *(float2*)&posk[r2 * 128 + pc] = make_float2(v10, v11);
            }
        }
}

// ---- GEMM 2: [q|k|v|posq] up-projections, route by column range -----------
__global__ __launch_bounds__(256, 1)
void tgemm_up(const __nv_bfloat16* __restrict__ lh, const __nv_bfloat16* __restrict__ ll,
              __nv_bfloat16* __restrict__ qch, __nv_bfloat16* __restrict__ qcl,
              __nv_bfloat16* __restrict__ kch, __nv_bfloat16* __restrict__ kcl,
              float* __restrict__ vmain, float* __restrict__ posq)
{
    extern __shared__ char smb[];
    const long m0 = blockIdx.y * 128L, n0 = blockIdx.x * 128L;
    const int route = (int)(n0 >> 11);                 // 0:q 1:k 2:v 3:posq
    const int aoff  = (route == 1) ? 512 : (route == 2) ? 1024 : 0;
    float acc[16][4];
    tg_core(lh, ll, 1536, aoff, g_wc2h, g_wc2l, m0, n0, LAT, smb, acc);

    const int tid = threadIdx.x, wid = tid >> 5, lane = tid & 31;
    const int wm = wid & 1, wn = wid >> 1;
    const long mb = m0 + wm * 64 + (lane >> 2);
    const int  nb = (int)n0 + wn * 32 + (lane & 3) * 2;
#pragma unroll
    for (int im = 0; im < 4; im++)
#pragma unroll
        for (int in_ = 0; in_ < 4; in_++) {
            const float* d = acc[im * 4 + in_];
            int col = nb + in_ * 8;
            float2 bv = *(const float2*)&g_bc2[col];
            float v00 = d[0] + bv.x, v01 = d[1] + bv.y;
            float v10 = d[2] + bv.x, v11 = d[3] + bv.y;
            long r1 = mb + im * 16, r2 = r1 + 8;
            if (route < 2) {
                int lc = col & 2047;
                long o = (long)(lc >> 7) * 192 + (lc & 127);
                __nv_bfloat16* oh = route == 0 ? qch : kch;
                __nv_bfloat16* ol = route == 0 ? qcl : kcl;
                uint32_t hi, lo;
                split2(v00, v01, hi, lo);
                *(uint32_t*)&oh[r1 * 3072 + o] = hi;
                *(uint32_t*)&ol[r1 * 3072 + o] = lo;
                split2(v10, v11, hi, lo);
                *(uint32_t*)&oh[r2 * 3072 + o] = hi;
                *(uint32_t*)&ol[r2 * 3072 + o] = lo;
            } else if (route == 2) {
                int vc = col - 4096;
                *(float2*)&vmain[r1 * DMODEL + vc] = make_float2(v00, v01);
                *(float2*)&vmain[r2 * DMODEL + vc] = make_float2(v10, v11);
            } else {
                int pc = col - 6144;
                *(float2*)&posq[r1 * 1024 + pc] = make_float2(v00, v01);
                *(float2*)&posq[r2 * 1024 + pc] = make_float2(v10, v11);
            }
        }
}

// ---- GEMM 3: generic (w_o) -------------------------------------------------
__global__ __launch_bounds__(256, 1)
void tgemm(const __nv_bfloat16* __restrict__ ah, const __nv_bfloat16* __restrict__ al,
           int lda,
           const __nv_bfloat16* __restrict__ bth, const __nv_bfloat16* __restrict__ btl,
           const float* __restrict__ bias, float* __restrict__ Cf, int ldc, int K)
{
    extern __shared__ char smb[];
    const long m0 = blockIdx.y * 128L, n0 = blockIdx.x * 128L;
    float acc[16][4];
    tg_core(ah, al, lda, 0, bth, btl, m0, n0, K, smb, acc);

    const int tid = threadIdx.x, wid = tid >> 5, lane = tid & 31;
    const int wm = wid & 1, wn = wid >> 1;
    const long mb = m0 + wm * 64 + (lane >> 2);
    const int  nb = (int)n0 + wn * 32 + (lane & 3) * 2;
#pragma unroll
    for (int im = 0; im < 4; im++)
#pragma unroll
        for (int in_ = 0; in_ < 4; in_++) {
            const float* d = acc[im * 4 + in_];
            int col = nb + in_ * 8;
            float2 bv = *(const float2*)&bias[col];
            long r1 = mb + im * 16, r2 = r1 + 8;
            *(float2*)&Cf[r1 * (long)ldc + col] = make_float2(d[0] + bv.x, d[1] + bv.y);
            *(float2*)&Cf[r2 * (long)ldc + col] = make_float2(d[2] + bv.x, d[3] + bv.y);
        }
}

// ======================= conversion kernels ================================
__global__ void split_f32(const float* __restrict__ s, __nv_bfloat16* __restrict__ h,
                          __nv_bfloat16* __restrict__ l, int n)
{
    int i = blockIdx.x * 256 + threadIdx.x;
    if (i >= n) return;
    float v = s[i];
    __nv_bfloat16 hv = __float2bfloat16(v);
    h[i] = hv;
    l[i] = __float2bfloat16(v - __bfloat162float(hv));
}

__device__ __forceinline__ void tsplit_body(
    const float* __restrict__ w, __nv_bfloat16* __restrict__ th,
    __nv_bfloat16* __restrict__ tl, int K, int N, int bx, int by)
{
    __shared__ float t[32][33];
    int nb = bx * 32, kb = by * 32;
    for (int r = threadIdx.y; r < 32; r += 8) {
        int n = nb + threadIdx.x;
        t[r][threadIdx.x] = (n < N) ? w[(long)(kb + r) * N + n] : 0.0f;
    }
    __syncthreads();
    for (int r = threadIdx.y; r < 32; r += 8) {
        long n = nb + r, k = kb + threadIdx.x;
        float v = t[threadIdx.x][r];
        __nv_bfloat16 hv = __float2bfloat16(v);
        th[n * K + k] = hv;
        tl[n * K + k] = __float2bfloat16(v - __bfloat162float(hv));
    }
}

__global__ void tsplit(const float* __restrict__ w, __nv_bfloat16* __restrict__ th,
                       __nv_bfloat16* __restrict__ tl, int K, int N)
{
    tsplit_body(w, th, tl, K, N, blockIdx.x, blockIdx.y);
}

// all weight transposes in one launch
#define TS_J0 3072
#define TS_J1 (TS_J0 + 256)
#define TS_J2 (TS_J1 + 1024)
#define TS_J3 (TS_J2 + 1024)
#define TS_J4 (TS_J3 + 1024)
#define TS_J5 (TS_J4 + 512)
#define TS_TOT (TS_J5 + 4096)

__global__ void tsplit_all(const float* __restrict__ wqkv, const float* __restrict__ wkp,
                           const float* __restrict__ wqu, const float* __restrict__ wku,
                           const float* __restrict__ wvu, const float* __restrict__ wqp,
                           const float* __restrict__ wo)
{
    int bid = blockIdx.x;
    const float* src; __nv_bfloat16 *th, *tl; int K, N, nbx, rb;
    if (bid < TS_J0)      { src = wqkv; th = g_wc1h;              tl = g_wc1l;              K = 2048; N = 1536; nbx = 48; rb = bid; }
    else if (bid < TS_J1) { src = wkp;  th = g_wc1h + 1536*2048;  tl = g_wc1l + 1536*2048;  K = 2048; N = 64;   nbx = 4;  rb = bid - TS_J0; }
    else if (bid < TS_J2) { src = wqu;  th = g_wc2h;              tl = g_wc2l;              K = 512;  N = 2048; nbx = 64; rb = bid - TS_J1; }
    else if (bid < TS_J3) { src = wku;  th = g_wc2h + 2048*512;   tl = g_wc2l + 2048*512;   K = 512;  N = 2048; nbx = 64; rb = bid - TS_J2; }
    else if (bid < TS_J4) { src = wvu;  th = g_wc2h + 4096*512;   tl = g_wc2l + 4096*512;   K = 512;  N = 2048; nbx = 64; rb = bid - TS_J3; }
    else if (bid < TS_J5) { src = wqp;  th = g_wc2h + 6144*512;   tl = g_wc2l + 6144*512;   K = 512;  N = 1024; nbx = 32; rb = bid - TS_J4; }
    else                  { src = wo;   th = g_woh;               tl = g_wol;               K = 2048; N = 2048; nbx = 64; rb = bid - TS_J5; }
    tsplit_body(src, th, tl, K, N, rb % nbx, rb / nbx);
}

__global__ void build_biases(const float* __restrict__ bqkv, const float* __restrict__ bkpos,
                             const float* __restrict__ bqup, const float* __restrict__ bkup,
                             const float* __restrict__ bvup, const float* __restrict__ bqpos)
{
    int i = blockIdx.x * 256 + threadIdx.x;
    if (i < 1664)
        g_bc1[i] = i < 1536 ? bqkv[i] : ((i - 1536) < 64 ? bkpos[i - 1536] : 0.0f);
    if (i < 7168) {
        int r = i >> 11, c = i & 2047;
        g_bc2[i] = r == 0 ? bqup[c] : r == 1 ? bkup[c] : r == 2 ? bvup[c] : bqpos[i - 6144];
    }
}

// ======================= fused RoPE -> bf16 split (merged) =================
#define LOG2_THETA_OVER_32 0.48780126482613787f
#define QROT (MROWS * 512)
#define KROT (MROWS * 32)

__global__ void rope_split(const float* __restrict__ pq, const float* __restrict__ pk,
                           __nv_bfloat16* __restrict__ qh, __nv_bfloat16* __restrict__ ql,
                           __nv_bfloat16* __restrict__ kh, __nv_bfloat16* __restrict__ kl)
{
    int idx = blockIdx.x * 256 + threadIdx.x;
    if (idx < QROT) {
        int r = idx >> 9, rem = idx & 511, h = rem >> 5, i = rem & 31;
        int s = r & (SS - 1);
        float ang = (float)s * exp2f(-(float)i * LOG2_THETA_OVER_32);
        float sn, cs; sincosf(ang, &sn, &cs);
        float v0 = pq[(long)r * 1024 + h * 64 + i];
        float v1 = pq[(long)r * 1024 + h * 64 + i + 32];
        float y0 = v0 * cs - v1 * sn;
        float y1 = v1 * cs + v0 * sn;
        long base = (long)r * 3072 + h * 192 + 128 + i;
        __nv_bfloat16 h0 = __float2bfloat16(y0);
        __nv_bfloat16 h1 = __float2bfloat16(y1);
        qh[base]      = h0;  ql[base]      = __float2bfloat16(y0 - __bfloat162float(h0));
        qh[base + 32] = h1;  ql[base + 32] = __float2bfloat16(y1 - __bfloat162float(h1));
    } else if (idx < QROT + KROT) {
        int k = idx - QROT;
        int r = k >> 5, i = k & 31;
        int s = r & (SS - 1);
        float ang = (float)s * exp2f(-(float)i * LOG2_THETA_OVER_32);
        float sn, cs; sincosf(ang, &sn, &cs);
        float v0 = pk[(long)r * 128 + i];
        float v1 = pk[(long)r * 128 + i + 32];
        float y0 = v0 * cs - v1 * sn;
        float y1 = v1 * cs + v0 * sn;
        __nv_bfloat16 h0 = __float2bfloat16(y0);
        __nv_bfloat16 h1 = __float2bfloat16(y1);
        __nv_bfloat16 l0 = __float2bfloat16(y0 - __bfloat162float(h0));
        __nv_bfloat16 l1 = __float2bfloat16(y1 - __bfloat162float(h1));
        long rb = (long)r * 3072 + 128 + i;
#pragma unroll
        for (int h = 0; h < 16; h++) {
            kh[rb + h * 192]      = h0;  kl[rb + h * 192]      = l0;
            kh[rb + h * 192 + 32] = h1;  kl[rb + h * 192 + 32] = l1;
        }
    }
}

// ======================= tensor-core flash attention =======================
#define AQH 0
#define AQL 49152
#define AKH 98304
#define AKL 122880
#define AVH 147456
#define AVL 163840
#define APH 180224
#define APL 196608
#define ATTN_SMEM 212992

__device__ __forceinline__ uint32_t sw384(int row, int seg) {
    return row * 384 + (((seg & 24) | ((seg ^ row) & 7)) << 4);
}
__device__ __forceinline__ uint32_t sw128s(int row, int seg) {
    return row * 128 + (((seg ^ row) & 7) << 4);
}

__global__ __launch_bounds__(256, 1)
void attn_mma(const __nv_bfloat16* __restrict__ qch, const __nv_bfloat16* __restrict__ qcl,
              const __nv_bfloat16* __restrict__ kch, const __nv_bfloat16* __restrict__ kcl,
              const __nv_bfloat16* __restrict__ vth, const __nv_bfloat16* __restrict__ vtl,
              __nv_bfloat16* __restrict__ obh, __nv_bfloat16* __restrict__ obl)
{
    extern __shared__ char smb[];
    const uint32_t sb = s2u(smb);
    const int tid = threadIdx.x, lane = tid & 31, w = tid >> 5;
    const int bh = blockIdx.y, b = bh >> 4, h = bh & 15;
    const int qti = (int)gridDim.x - 1 - (int)blockIdx.x;
    const int m0 = qti * 128, nk = 2 * qti + 2;
    const long rowbase = (long)b * SS;
    const float scale = 0.07216878364870323f;

#pragma unroll
    for (int i = 0; i < 12; i++) {
        int v = tid + i * 256;
        int row = v / 24, seg = v - row * 24;
        long g = ((rowbase + m0 + row) * 16 + h) * 192 + seg * 8;
        cp16(smb + AQH + sw384(row, seg), qch + g);
        cp16(smb + AQL + sw384(row, seg), qcl + g);
    }
#pragma unroll
    for (int i = 0; i < 6; i++) {
        int v = tid + i * 256;
        int row = v / 24, seg = v - row * 24;
        long g = ((rowbase + row) * 16 + h) * 192 + seg * 8;
        cp16(smb + AKH + sw384(row, seg), kch + g);
        cp16(smb + AKL + sw384(row, seg), kcl + g);
    }
#pragma unroll
    for (int i = 0; i < 4; i++) {
        int v = tid + i * 256;
        int row = v >> 3, seg = v & 7;
        long g = (long)(h * 128 + row) * MROWS + rowbase + seg * 8;
        cp16(smb + AVH + sw128s(row, seg), vth + g);
        cp16(smb + AVL + sw128s(row, seg), vtl + g);
    }
    asm volatile("cp.async.commit_group;\n" ::: "memory");

    float oc[16][4];
#pragma unroll
    for (int i = 0; i < 16; i++)
#pragma unroll
        for (int j = 0; j < 4; j++) oc[i][j] = 0.0f;
    float mi[2] = {-1e30f, -1e30f}, li[2] = {0.0f, 0.0f};

    const int a_lrow = lane & 15;
    const int a_ksel = lane >> 4;
    const int b_lrow = (lane & 7) + ((lane >> 4) << 3);
    const int b_ksel = (lane >> 3) & 1;

    for (int t = 0; t < nk; ++t) {
        asm volatile("cp.async.wait_group 0;\n" ::: "memory");
        __syncthreads();
        const int n0 = t * 64;

        float sc[8][4];
#pragma unroll
        for (int i = 0; i < 8; i++)
#pragma unroll
            for (int j = 0; j < 4; j++) sc[i][j] = 0.0f;

#pragma unroll
        for (int ks = 0; ks < 12; ks++) {
            uint32_t afh[4], afl[4];
            {
                int row = w * 16 + a_lrow;
                int seg = ks * 2 + a_ksel;
                ldsm_x4(afh, sb + AQH + sw384(row, seg));
                ldsm_x4(afl, sb + AQL + sw384(row, seg));
            }
#pragma unroll
            for (int blk = 0; blk < 4; blk++) {
                uint32_t bh_[4], bl_[4];
                int row = blk * 16 + b_lrow;
                int seg = ks * 2 + b_ksel;
                ldsm_x4(bh_, sb + AKH + sw384(row, seg));
                ldsm_x4(bl_, sb + AKL + sw384(row, seg));
#pragma unroll
                for (int hf = 0; hf < 2; hf++) {
                    float* d = sc[blk * 2 + hf];
                    mma_bf16(d, afh, bh_[hf * 2], bh_[hf * 2 + 1]);
                    mma_bf16(d, afh, bl_[hf * 2], bl_[hf * 2 + 1]);
                    mma_bf16(d, afl, bh_[hf * 2], bh_[hf * 2 + 1]);
                }
            }
        }

        const bool diag = (t >= 2 * qti);
        const int rbase = m0 + w * 16 + (lane >> 2);
        const int cbase = n0 + (lane & 3) * 2;
#pragma unroll
        for (int a = 0; a < 2; a++) {
            float m_t = -1e30f;
#pragma unroll
            for (int nb = 0; nb < 8; nb++)
#pragma unroll
                for (int c = 0; c < 2; c++) {
                    float s = sc[nb][2 * a + c] * scale;
                    if (diag && (cbase + nb * 8 + c) > (rbase + 8 * a)) s = -1e30f;
                    sc[nb][2 * a + c] = s;
                    m_t = fmaxf(m_t, s);
                }
            m_t = fmaxf(m_t, __shfl_xor_sync(0xffffffffu, m_t, 1));
            m_t = fmaxf(m_t, __shfl_xor_sync(0xffffffffu, m_t, 2));
            float mnew = fmaxf(mi[a], m_t);
            float alpha = __expf(mi[a] - mnew);
            float rsum = 0.0f;
#pragma unroll
            for (int nb = 0; nb < 8; nb++)
#pragma unroll
                for (int c = 0; c < 2; c++) {
                    float p = __expf(sc[nb][2 * a + c] - mnew);
                    sc[nb][2 * a + c] = p;
                    rsum += p;
                }
            rsum += __shfl_xor_sync(0xffffffffu, rsum, 1);
            rsum += __shfl_xor_sync(0xffffffffu, rsum, 2);
            li[a] = li[a] * alpha + rsum;
            mi[a] = mnew;
#pragma unroll
            for (int nb2 = 0; nb2 < 16; nb2++) {
                oc[nb2][2 * a]     *= alpha;
                oc[nb2][2 * a + 1] *= alpha;
            }
        }

#pragma unroll
        for (int a = 0; a < 2; a++) {
            int row = w * 16 + (lane >> 2) + 8 * a;
#pragma unroll
            for (int nb = 0; nb < 8; nb++) {
                uint32_t hi, lo;
                split2(sc[nb][2 * a], sc[nb][2 * a + 1], hi, lo);
                uint32_t off = sw128s(row, nb) + (lane & 3) * 4;
                *(uint32_t*)(smb + APH + off) = hi;
                *(uint32_t*)(smb + APL + off) = lo;
            }
        }
        __syncwarp();
        __syncthreads();

        if (t + 1 < nk) {
#pragma unroll
            for (int i = 0; i < 6; i++) {
                int v = tid + i * 256;
                int row = v / 24, seg = v - row * 24;
                long g = ((rowbase + n0 + 64 + row) * 16 + h) * 192 + seg * 8;
                cp16(smb + AKH + sw384(row, seg), kch + g);
                cp16(smb + AKL + sw384(row, seg), kcl + g);
            }
            asm volatile("cp.async.commit_group;\n" ::: "memory");
        }

#pragma unroll
        for (int ks = 0; ks < 4; ks++) {
            uint32_t aph[4], apl[4];
            {
                int row = w * 16 + a_lrow;
                int seg = ks * 2 + a_ksel;
                ldsm_x4(aph, sb + APH + sw128s(row, seg));
                ldsm_x4(apl, sb + APL + sw128s(row, seg));
            }
#pragma unroll
            for (int blk = 0; blk < 8; blk++) {
                uint32_t bh_[4], bl_[4];
                int row = blk * 16 + b_lrow;
                int seg = ks * 2 + b_ksel;
                ldsm_x4(bh_, sb + AVH + sw128s(row, seg));
                ldsm_x4(bl_, sb + AVL + sw128s(row, seg));
#pragma unroll
                for (int hf = 0; hf < 2; hf++) {
                    float* d = oc[blk * 2 + hf];
                    mma_bf16(d, aph, bh_[hf * 2], bh_[hf * 2 + 1]);
                    mma_bf16(d, aph, bl_[hf * 2], bl_[hf * 2 + 1]);
                    mma_bf16(d, apl, bh_[hf * 2], bh_[hf * 2 + 1]);
                }
            }
        }
        __syncthreads();

        if (t + 1 < nk) {
#pragma unroll
            for (int i = 0; i < 4; i++) {
                int v = tid + i * 256;
                int row = v >> 3, seg = v & 7;
                long g = (long)(h * 128 + row) * MROWS + rowbase + n0 + 64 + seg * 8;
                cp16(smb + AVH + sw128s(row, seg), vth + g);
                cp16(smb + AVL + sw128s(row, seg), vtl + g);
            }
            asm volatile("cp.async.commit_group;\n" ::: "memory");
        }
    }

#pragma unroll
    for (int nb2 = 0; nb2 < 16; nb2++) {
        int dcol = nb2 * 8 + (lane & 3) * 2;
#pragma unroll
        for (int a = 0; a < 2; a++) {
            long row = rowbase + m0 + w * 16 + (lane >> 2) + 8 * a;
            float inv = 1.0f / li[a];
            uint32_t hi, lo;
            split2(oc[nb2][2 * a] * inv, oc[nb2][2 * a + 1] * inv, hi, lo);
            long idx = row * DMODEL + h * HD + dcol;
            *(uint32_t*)&obh[idx] = hi;
            *(uint32_t*)&obl[idx] = lo;
        }
    }
}

// ======================= launch ============================================
#define SYM(p, s) cudaGetSymbolAddress((void**)&p, s)

extern "C" void kernel_launch(void* const* d_in, const int* in_sizes, int n_in,
                              void* d_out, int out_size)
{
    const float* x      = (const float*)d_in[0];
    const float* w_qkv  = (const float*)d_in[1];
    const float* b_qkv  = (const float*)d_in[2];
    const float* w_qup  = (const float*)d_in[3];
    const float* b_qup  = (const float*)d_in[4];
    const float* w_kup  = (const float*)d_in[5];
    const float* b_kup  = (const float*)d_in[6];
    const float* w_vup  = (const float*)d_in[7];
    const float* b_vup  = (const float*)d_in[8];
    const float* w_qpos = (const float*)d_in[9];
    const float* b_qpos = (const float*)d_in[10];
    const float* w_kpos = (const float*)d_in[11];
    const float* b_kpos = (const float*)d_in[12];
    const float* w_o    = (const float*)d_in[13];
    const float* b_o    = (const float*)d_in[14];
    float* out = (float*)d_out;

    float *vmain, *posq, *posk;
    SYM(vmain, g_vmain); SYM(posq, g_posq); SYM(posk, g_posk);
    __nv_bfloat16 *xh,*xl,*lh,*ll,*abh,*abl,*woh,*wol,
                  *qch,*qcl,*kch,*kcl,*vth,*vtl;
    SYM(xh,g_xh); SYM(xl,g_xl); SYM(lh,g_lh); SYM(ll,g_ll);
    SYM(abh,g_abh); SYM(abl,g_abl);
    SYM(woh,g_woh); SYM(wol,g_wol);
    SYM(qch,g_qch); SYM(qcl,g_qcl); SYM(kch,g_kch); SYM(kcl,g_kcl);
    SYM(vth,g_vth); SYM(vtl,g_vtl);

    cudaFuncSetAttribute(tgemm_qkv, cudaFuncAttributeMaxDynamicSharedMemorySize, TG_SMEM);
    cudaFuncSetAttribute(tgemm_up,  cudaFuncAttributeMaxDynamicSharedMemorySize, TG_SMEM);
    cudaFuncSetAttribute(tgemm,     cudaFuncAttributeMaxDynamicSharedMemorySize, TG_SMEM);
    cudaFuncSetAttribute(attn_mma,  cudaFuncAttributeMaxDynamicSharedMemorySize, ATTN_SMEM);
    dim3 t8(32, 8);

    // 1) all weight transposes, one launch
    tsplit_all<<<TS_TOT, t8>>>(w_qkv, w_kpos, w_qup, w_kup, w_vup, w_qpos, w_o);
    // 2) concatenated biases
    build_biases<<<28, 256>>>(b_qkv, b_kpos, b_qup, b_kup, b_vup, b_qpos);
    // 3) split x
    split_f32<<<(MROWS * DMODEL) / 256, 256>>>(x, xh, xl, MROWS * DMODEL);
    // 4) [latent | posk] = x @ wc1
    tgemm_qkv<<<dim3(13, 32), 256, TG_SMEM>>>(xh, xl, lh, ll, posk);
    // 5) [q|k|v|posq] = latent-slices @ wc2 (routed)
    tgemm_up<<<dim3(56, 32), 256, TG_SMEM>>>(lh, ll, qch, qcl, kch, kcl, vmain, posq);
    // 6) RoPE (q+k merged) -> bf16 split pos-columns
    rope_split<<<(QROT + KROT + 255) / 256, 256>>>(posq, posk, qch, qcl, kch, kcl);
    // 7) V transpose+split
    tsplit<<<dim3(2048 / 32, MROWS / 32), t8>>>(vmain, vth, vtl, MROWS, DMODEL);
    // 8) attention
    attn_mma<<<dim3(SS / 128, BB * NHD), 256, ATTN_SMEM>>>(
        qch, qcl, kch, kcl, vth, vtl, abh, abl);
    // 9) out = attn @ w_o
    tgemm<<<dim3(16, 32), 256, TG_SMEM>>>(abh, abl, DMODEL, woh, wol,
                                          b_o, out, DMODEL, DMODEL);
}